// round 1
// baseline (speedup 1.0000x reference)
#include <cuda_runtime.h>
#include <math.h>

// Problem constants
#define EB 1024     // embed dim
#define DH 64       // head dim
#define NH 16       // heads
#define BB 8
#define LL 4096
#define MT (BB*LL)          // 32768 tokens
#define GN (2*EB + DH)      // 2112 = [a | b | dx] columns
#define GK EB

// ---------------- scratch (static device allocations) ----------------
__device__ float g_a [ (size_t)MT * EB ];   // [B,L,H,D] tanh gate
__device__ float g_b [ (size_t)MT * EB ];   // [B,L,H,D] additive gate
__device__ float g_hs[ (size_t)MT * EB ];   // [B,L,H,D] scan output
__device__ float g_dx[ (size_t)MT * DH ];   // [B,L,D]
__device__ float g_wpack[ (size_t)GK * GN ];// packed [K, N] weights

// ---------------- kernel 0: pack weights [K,N] ----------------
__global__ void pack_w_kernel(const float* __restrict__ Wa,
                              const float* __restrict__ Wb,
                              const float* __restrict__ Wd)
{
    int idx = blockIdx.x * 256 + threadIdx.x;
    if (idx >= GK * GN) return;
    int e = idx / GN;
    int n = idx % GN;
    float v;
    if (n < 1024) {
        v = Wa[(size_t)(n >> 6) * (EB * DH) + (size_t)e * DH + (n & 63)];
    } else if (n < 2048) {
        int n2 = n - 1024;
        v = Wb[(size_t)(n2 >> 6) * (EB * DH) + (size_t)e * DH + (n2 & 63)];
    } else {
        v = Wd[(size_t)e * DH + (n - 2048)];
    }
    g_wpack[idx] = v;
}

// ---------------- kernel 1: gates GEMM ----------------
// C[M=32768, N=2112] = emb[M,K=1024] @ Wpack[K,N], fused bias+tanh epilogue.
// Tile 128x64x16, 256 threads, 8x4 microtile, double-buffered smem.
__global__ void __launch_bounds__(256)
gemm_gates_kernel(const float* __restrict__ emb,
                  const float* __restrict__ ba,
                  const float* __restrict__ bb,
                  const float* __restrict__ bd)
{
    __shared__ float As[2][16][132];   // [buf][k][m] transposed, pad to 132
    __shared__ float Bs[2][16][64];    // [buf][k][n]

    const int tid = threadIdx.x;
    const long m0 = (long)blockIdx.y * 128;
    const int  n0 = blockIdx.x * 64;

    const int arow = tid >> 2;          // 0..63
    const int ak   = (tid & 3) * 4;     // 0,4,8,12
    const int brow = tid >> 4;          // 0..15
    const int bcol = (tid & 15) * 4;    // 0..60

    const int ty = tid >> 4;            // 0..15 -> rows ty*8..+7
    const int tx = tid & 15;            // 0..15 -> cols tx*4..+3

    float acc[8][4];
#pragma unroll
    for (int i = 0; i < 8; i++)
#pragma unroll
        for (int j = 0; j < 4; j++) acc[i][j] = 0.f;

    const float* A0p = emb + (m0 + arow) * (long)GK;
    const float* A1p = emb + (m0 + arow + 64) * (long)GK;

    float4 a0, a1, b0;
    // prologue: tile 0
    a0 = *(const float4*)(A0p + ak);
    a1 = *(const float4*)(A1p + ak);
    b0 = *(const float4*)(g_wpack + (size_t)brow * GN + n0 + bcol);
    {
        const float* av0 = &a0.x;
        const float* av1 = &a1.x;
#pragma unroll
        for (int q = 0; q < 4; q++) {
            As[0][ak + q][arow]      = av0[q];
            As[0][ak + q][arow + 64] = av1[q];
        }
        *(float4*)&Bs[0][brow][bcol] = b0;
    }
    __syncthreads();

    for (int kt = 0; kt < 64; kt++) {
        const int cur = kt & 1;
        if (kt < 63) {
            const int kb = (kt + 1) * 16;
            a0 = *(const float4*)(A0p + kb + ak);
            a1 = *(const float4*)(A1p + kb + ak);
            b0 = *(const float4*)(g_wpack + (size_t)(kb + brow) * GN + n0 + bcol);
        }
#pragma unroll
        for (int kk = 0; kk < 16; kk++) {
            float4 x0 = *(const float4*)&As[cur][kk][ty * 8];
            float4 x1 = *(const float4*)&As[cur][kk][ty * 8 + 4];
            float4 y  = *(const float4*)&Bs[cur][kk][tx * 4];
            const float xr[8] = {x0.x,x0.y,x0.z,x0.w,x1.x,x1.y,x1.z,x1.w};
            const float yr[4] = {y.x,y.y,y.z,y.w};
#pragma unroll
            for (int i = 0; i < 8; i++)
#pragma unroll
                for (int j = 0; j < 4; j++) acc[i][j] = fmaf(xr[i], yr[j], acc[i][j]);
        }
        if (kt < 63) {
            const int nxt = cur ^ 1;
            const float* av0 = &a0.x;
            const float* av1 = &a1.x;
#pragma unroll
            for (int q = 0; q < 4; q++) {
                As[nxt][ak + q][arow]      = av0[q];
                As[nxt][ak + q][arow + 64] = av1[q];
            }
            *(float4*)&Bs[nxt][brow][bcol] = b0;
            __syncthreads();
        }
    }

    // epilogue: branch is uniform per block (n tile aligned to 64)
#pragma unroll
    for (int i = 0; i < 8; i++) {
        const long m = m0 + ty * 8 + i;
#pragma unroll
        for (int j = 0; j < 4; j++) {
            const int n = n0 + tx * 4 + j;
            const float c = acc[i][j];
            if (n < 1024) {
                g_a[m * EB + n] = tanhf(c + ba[n]);
            } else if (n < 2048) {
                g_b[m * EB + (n - 1024)] = c + bb[n - 1024];
            } else {
                g_dx[m * DH + (n - 2048)] = c + bd[n - 2048];
            }
        }
    }
}

// ---------------- kernel 2: linear recurrence scan ----------------
// one block per (b,h): 64 threads, each owns one d channel, loops over L
__global__ void __launch_bounds__(64)
scan_kernel()
{
    const int bh = blockIdx.x;
    const int d  = threadIdx.x;
    const int b  = bh >> 4;
    const int h  = bh & 15;
    size_t base = (size_t)b * LL * EB + (size_t)h * DH + d;
    float hv = 0.f;
#pragma unroll 8
    for (int l = 0; l < LL; l++) {
        size_t idx = base + (size_t)l * EB;
        float av = g_a[idx];
        float bv = g_b[idx];
        hv = fmaf(av, hv, bv);
        g_hs[idx] = hv;
    }
}

// ---------------- kernel 3: fused per-token epilogue ----------------
// 32 tokens per block, 256 threads: thread (tt=tid>>3, eg=tid&7) owns
// e = eg*8 .. eg*8+7 of token tt. Everything else staged in shared.
#define HS_STRIDE 68
#define G_STRIDE  264
#define SM_FLOATS (16384 + 16384 + 4096 + 32*HS_STRIDE + 32*G_STRIDE + 32*HS_STRIDE)
#define SM_BYTES  (SM_FLOATS * 4)

__device__ __forceinline__ float grp8_sum(float v) {
    v += __shfl_xor_sync(0xffffffffu, v, 1);
    v += __shfl_xor_sync(0xffffffffu, v, 2);
    v += __shfl_xor_sync(0xffffffffu, v, 4);
    return v;
}

__global__ void __launch_bounds__(256)
post_kernel(const float* __restrict__ Wc,  const float* __restrict__ bc,
            const float* __restrict__ head_w,
            const float* __restrict__ hn_g, const float* __restrict__ hn_b,
            const float* __restrict__ W1,  const float* __restrict__ b1,
            const float* __restrict__ W2,  const float* __restrict__ b2,
            const float* __restrict__ Wp,  const float* __restrict__ bp,
            const float* __restrict__ ng,  const float* __restrict__ nb,
            float* __restrict__ out)
{
    extern __shared__ float sm[];
    const int tid = threadIdx.x;
    const int tt  = tid >> 3;     // token within block (0..31)
    const int eg  = tid & 7;
    const int e0  = eg * 8;
    const long token0 = (long)blockIdx.x * 32;
    const long tok = token0 + tt;

    // ---- Phase A layout ----
    float* sWc = sm;           // 4096
    float* sHs = sm + 4096;    // 32*HS_STRIDE

    float dxv[8], acc[8];
#pragma unroll
    for (int k = 0; k < 8; k++) {
        dxv[k] = g_dx[tok * DH + e0 + k];
        acc[k] = dxv[k];
    }

    for (int h = 0; h < NH; h++) {
        __syncthreads();
#pragma unroll
        for (int i = 0; i < 16; i++)
            sWc[tid + i * 256] = Wc[(size_t)h * 4096 + tid + i * 256];
#pragma unroll
        for (int i = 0; i < 8; i++) {
            int idx = tid + i * 256;          // 0..2047 = t*64+d
            int t = idx >> 6, d = idx & 63;
            sHs[t * HS_STRIDE + d] = g_hs[(token0 + t) * (long)EB + h * DH + d];
        }
        __syncthreads();

        float o[8];
#pragma unroll
        for (int k = 0; k < 8; k++) o[k] = bc[h * DH + e0 + k] + dxv[k];
#pragma unroll 8
        for (int d = 0; d < 64; d++) {
            float hv = sHs[tt * HS_STRIDE + d];
            float4 w0 = *(const float4*)&sWc[d * 64 + e0];
            float4 w1 = *(const float4*)&sWc[d * 64 + e0 + 4];
            o[0] = fmaf(hv, w0.x, o[0]); o[1] = fmaf(hv, w0.y, o[1]);
            o[2] = fmaf(hv, w0.z, o[2]); o[3] = fmaf(hv, w0.w, o[3]);
            o[4] = fmaf(hv, w1.x, o[4]); o[5] = fmaf(hv, w1.y, o[5]);
            o[6] = fmaf(hv, w1.z, o[6]); o[7] = fmaf(hv, w1.w, o[7]);
        }
        // per-head LayerNorm over 64 dims (8 lanes x 8 regs)
        float s1 = 0.f, s2 = 0.f;
#pragma unroll
        for (int k = 0; k < 8; k++) { s1 += o[k]; s2 += o[k] * o[k]; }
        s1 = grp8_sum(s1); s2 = grp8_sum(s2);
        float mean = s1 * (1.f / 64.f);
        float var  = s2 * (1.f / 64.f) - mean * mean;
        float rstd = rsqrtf(var + 1e-5f);
        float hw = head_w[h];
#pragma unroll
        for (int k = 0; k < 8; k++) {
            float lnv = (o[k] - mean) * rstd * hn_g[h * DH + e0 + k] + hn_b[h * DH + e0 + k];
            acc[k] = fmaf(hw, lnv, acc[k]);
        }
    }

    // z = acc/H ; u = z + LN(z)
    float u[8];
    {
        float s1 = 0.f, s2 = 0.f;
#pragma unroll
        for (int k = 0; k < 8; k++) {
            acc[k] *= (1.f / (float)NH);
            s1 += acc[k]; s2 += acc[k] * acc[k];
        }
        s1 = grp8_sum(s1); s2 = grp8_sum(s2);
        float mean = s1 * (1.f / 64.f);
        float var  = s2 * (1.f / 64.f) - mean * mean;
        float rstd = rsqrtf(var + 1e-5f);
#pragma unroll
        for (int k = 0; k < 8; k++)
            u[k] = acc[k] + (acc[k] - mean) * rstd * ng[e0 + k] + nb[e0 + k];
    }

    __syncthreads();   // done with Phase A shared

    // ---- Phase B layout (overlays Phase A) ----
    float* sW1  = sm;                          // 16384
    float* sW2  = sm + 16384;                  // 16384
    float* sWp  = sm + 32768;                  // 4096
    float* sU   = sm + 36864;                  // 32*HS_STRIDE
    float* sG   = sm + 36864 + 32 * HS_STRIDE; // 32*G_STRIDE
    float* sHo  = sG + 32 * G_STRIDE;          // 32*HS_STRIDE

    for (int i = tid; i < 16384; i += 256) sW1[i] = W1[i];
    for (int i = tid; i < 16384; i += 256) sW2[i] = W2[i];
    for (int i = tid; i < 4096;  i += 256) sWp[i] = Wp[i];
#pragma unroll
    for (int k = 0; k < 8; k++) sU[tt * HS_STRIDE + e0 + k] = u[k];
    __syncthreads();

    // FFN mid: j = eg + 8*kk  (conflict-free W1 reads)
#pragma unroll 4
    for (int kk = 0; kk < 32; kk++) {
        int j = eg + 8 * kk;
        float m = b1[j];
#pragma unroll 8
        for (int d = 0; d < 64; d++)
            m = fmaf(sU[tt * HS_STRIDE + d], sW1[d * 256 + j], m);
        float g = 0.5f * m * (1.f + erff(m * 0.70710678118654752f));
        sG[tt * G_STRIDE + j] = g;
    }
    __syncthreads();

    float o2[8];
#pragma unroll
    for (int k = 0; k < 8; k++) o2[k] = b2[e0 + k];
#pragma unroll 8
    for (int j = 0; j < 256; j++) {
        float gv = sG[tt * G_STRIDE + j];
        float4 w0 = *(const float4*)&sW2[j * 64 + e0];
        float4 w1 = *(const float4*)&sW2[j * 64 + e0 + 4];
        o2[0] = fmaf(gv, w0.x, o2[0]); o2[1] = fmaf(gv, w0.y, o2[1]);
        o2[2] = fmaf(gv, w0.z, o2[2]); o2[3] = fmaf(gv, w0.w, o2[3]);
        o2[4] = fmaf(gv, w1.x, o2[4]); o2[5] = fmaf(gv, w1.y, o2[5]);
        o2[6] = fmaf(gv, w1.z, o2[6]); o2[7] = fmaf(gv, w1.w, o2[7]);
    }
#pragma unroll
    for (int k = 0; k < 8; k++)
        sHo[tt * HS_STRIDE + e0 + k] = u[k] + o2[k];
    __syncthreads();

    float fo[8];
#pragma unroll
    for (int k = 0; k < 8; k++) fo[k] = bp[e0 + k];
#pragma unroll 8
    for (int d = 0; d < 64; d++) {
        float hv = sHo[tt * HS_STRIDE + d];
        float4 w0 = *(const float4*)&sWp[d * 64 + e0];
        float4 w1 = *(const float4*)&sWp[d * 64 + e0 + 4];
        fo[0] = fmaf(hv, w0.x, fo[0]); fo[1] = fmaf(hv, w0.y, fo[1]);
        fo[2] = fmaf(hv, w0.z, fo[2]); fo[3] = fmaf(hv, w0.w, fo[3]);
        fo[4] = fmaf(hv, w1.x, fo[4]); fo[5] = fmaf(hv, w1.y, fo[5]);
        fo[6] = fmaf(hv, w1.z, fo[6]); fo[7] = fmaf(hv, w1.w, fo[7]);
    }
#pragma unroll
    for (int k = 0; k < 8; k++)
        out[tok * DH + e0 + k] = fo[k];
}

// ---------------- launch ----------------
extern "C" void kernel_launch(void* const* d_in, const int* in_sizes, int n_in,
                              void* d_out, int out_size)
{
    const float* emb    = (const float*)d_in[0];
    const float* Wa     = (const float*)d_in[1];
    const float* ba     = (const float*)d_in[2];
    const float* Wb     = (const float*)d_in[3];
    const float* bb     = (const float*)d_in[4];
    const float* Wc     = (const float*)d_in[5];
    const float* bc     = (const float*)d_in[6];
    const float* head_w = (const float*)d_in[7];
    const float* hn_g   = (const float*)d_in[8];
    const float* hn_b   = (const float*)d_in[9];
    const float* Wd     = (const float*)d_in[10];
    const float* bd     = (const float*)d_in[11];
    const float* W1     = (const float*)d_in[12];
    const float* b1     = (const float*)d_in[13];
    const float* W2     = (const float*)d_in[14];
    const float* b2     = (const float*)d_in[15];
    const float* Wp     = (const float*)d_in[16];
    const float* bp     = (const float*)d_in[17];
    const float* ng     = (const float*)d_in[18];
    const float* nb     = (const float*)d_in[19];
    float* out = (float*)d_out;

    cudaFuncSetAttribute(post_kernel, cudaFuncAttributeMaxDynamicSharedMemorySize, SM_BYTES);

    pack_w_kernel<<<(GK * GN + 255) / 256, 256>>>(Wa, Wb, Wd);

    dim3 ggrid(GN / 64, MT / 128);
    gemm_gates_kernel<<<ggrid, 256>>>(emb, ba, bb, bd);

    scan_kernel<<<BB * NH, 64>>>();

    post_kernel<<<MT / 32, 256, SM_BYTES>>>(Wc, bc, head_w, hn_g, hn_b,
                                            W1, b1, W2, b2, Wp, bp, ng, nb, out);
}

// round 3
// speedup vs baseline: 1.3494x; 1.3494x over previous
#include <cuda_runtime.h>
#include <cuda_bf16.h>
#include <math.h>
#include <stdint.h>

// Problem constants
#define EB 1024     // embed dim
#define DH 64       // head dim
#define NH 16       // heads
#define BB 8
#define LL 4096
#define MT (BB*LL)          // 32768 tokens
#define GN (2*EB + DH)      // 2112 real columns  [a | b | dx]
#define GNP 2176            // padded to 17 tiles of 128
#define GK EB

// ---------------- scratch ----------------
__device__ float g_a [ (size_t)MT * EB ];   // [B,L,H,D] tanh gate
__device__ float g_b [ (size_t)MT * EB ];   // [B,L,H,D] additive gate
__device__ float g_hs[ (size_t)MT * EB ];   // [B,L,H,D] scan output
__device__ float g_dx[ (size_t)MT * DH ];   // [B,L,D]

__device__ __nv_bfloat16 g_ehi[ (size_t)MT * GK ];
__device__ __nv_bfloat16 g_elo[ (size_t)MT * GK ];
__device__ __nv_bfloat16 g_whi[ (size_t)GNP * GK ];  // [n][k] K-major
__device__ __nv_bfloat16 g_wlo[ (size_t)GNP * GK ];

// ---------------- helpers ----------------
__device__ __forceinline__ uint32_t smem_u32(const void* p) {
    uint32_t r;
    asm("{ .reg .u64 t; cvta.to.shared.u64 t, %1; cvt.u32.u64 %0, t; }" : "=r"(r) : "l"(p));
    return r;
}

__device__ __forceinline__ void cp_async16(uint32_t dst, const void* src) {
    asm volatile("cp.async.cg.shared.global [%0], [%1], 16;" :: "r"(dst), "l"(src) : "memory");
}
__device__ __forceinline__ void cp_commit() {
    asm volatile("cp.async.commit_group;" ::: "memory");
}

__device__ __forceinline__ void ldmatrix_x4(uint32_t* r, uint32_t addr) {
    asm volatile("ldmatrix.sync.aligned.m8n8.x4.shared.b16 {%0,%1,%2,%3}, [%4];"
                 : "=r"(r[0]), "=r"(r[1]), "=r"(r[2]), "=r"(r[3]) : "r"(addr));
}

__device__ __forceinline__ void mma_bf16(float* c, const uint32_t* a, uint32_t b0, uint32_t b1) {
    asm volatile(
        "mma.sync.aligned.m16n8k16.row.col.f32.bf16.bf16.f32 "
        "{%0,%1,%2,%3}, {%4,%5,%6,%7}, {%8,%9}, {%0,%1,%2,%3};"
        : "+f"(c[0]), "+f"(c[1]), "+f"(c[2]), "+f"(c[3])
        : "r"(a[0]), "r"(a[1]), "r"(a[2]), "r"(a[3]), "r"(b0), "r"(b1));
}

// ---------------- kernel: fp32 -> bf16 hi/lo split of emb ----------------
__global__ void conv_emb_kernel(const float* __restrict__ emb)
{
    size_t i = ((size_t)blockIdx.x * 256 + threadIdx.x) * 4;
    float4 x = *(const float4*)(emb + i);
    __nv_bfloat16 h0 = __float2bfloat16(x.x);
    __nv_bfloat16 h1 = __float2bfloat16(x.y);
    __nv_bfloat16 h2 = __float2bfloat16(x.z);
    __nv_bfloat16 h3 = __float2bfloat16(x.w);
    __nv_bfloat162 hi01, hi23, lo01, lo23;
    hi01.x = h0; hi01.y = h1; hi23.x = h2; hi23.y = h3;
    lo01.x = __float2bfloat16(x.x - __bfloat162float(h0));
    lo01.y = __float2bfloat16(x.y - __bfloat162float(h1));
    lo23.x = __float2bfloat16(x.z - __bfloat162float(h2));
    lo23.y = __float2bfloat16(x.w - __bfloat162float(h3));
    *(__nv_bfloat162*)(g_ehi + i)     = hi01;
    *(__nv_bfloat162*)(g_ehi + i + 2) = hi23;
    *(__nv_bfloat162*)(g_elo + i)     = lo01;
    *(__nv_bfloat162*)(g_elo + i + 2) = lo23;
}

// ---------------- kernel: pack weights [n][k] K-major, bf16 hi/lo ----------------
__global__ void pack_w_kernel(const float* __restrict__ Wa,
                              const float* __restrict__ Wb,
                              const float* __restrict__ Wd)
{
    size_t idx = (size_t)blockIdx.x * 256 + threadIdx.x;
    if (idx >= (size_t)GNP * GK) return;
    int n = (int)(idx >> 10);
    int k = (int)(idx & 1023);
    float v = 0.f;
    if (n < 1024) {
        v = Wa[(size_t)(n >> 6) * (EB * DH) + (size_t)k * DH + (n & 63)];
    } else if (n < 2048) {
        int n2 = n - 1024;
        v = Wb[(size_t)(n2 >> 6) * (EB * DH) + (size_t)k * DH + (n2 & 63)];
    } else if (n < 2112) {
        v = Wd[(size_t)k * DH + (n - 2048)];
    }
    __nv_bfloat16 h = __float2bfloat16(v);
    g_whi[idx] = h;
    g_wlo[idx] = __float2bfloat16(v - __bfloat162float(h));
}

// ---------------- kernel: HMMA gates GEMM ----------------
// C[M=32768, N=2176] = E[M,K=1024] @ W^T[N,K] via bf16 split (3 mma per pair)
// CTA tile 128x128, 8 warps of 32x64, K-chunk 32, cp.async double-buffer.
#define KC 32
#define NKC (GK / KC)        // 32
#define AROWB 80             // smem bytes per row (64 data + pad, 16B aligned, cf-free ldmatrix)
#define TILEB (128 * AROWB)  // 10240
#define STAGEB (4 * TILEB)   // 40960
#define GEMM_SMEM (2 * STAGEB)  // 81920

__device__ __forceinline__ void gemm_prefetch(uint32_t sbase, int stage, int kc, int tid,
                                              const char* tp0, const char* tp1,
                                              const char* tp2, const char* tp3)
{
    const char* tp[4] = {tp0, tp1, tp2, tp3};
    uint32_t sst = sbase + stage * STAGEB;
    const size_t kb = (size_t)kc * KC * 2;   // byte offset in K
#pragma unroll
    for (int t = 0; t < 4; t++) {
#pragma unroll
        for (int j = 0; j < 2; j++) {
            int id  = tid + j * 256;         // 0..511
            int row = id >> 2;               // 0..127
            int c   = (id & 3) * 16;         // 0..48
            uint32_t dst = sst + t * TILEB + row * AROWB + c;
            const char* src = tp[t] + (size_t)row * (GK * 2) + kb + c;
            cp_async16(dst, src);
        }
    }
}

__global__ void __launch_bounds__(256, 1)
gemm_tc_kernel(const float* __restrict__ ba,
               const float* __restrict__ bb,
               const float* __restrict__ bd)
{
    extern __shared__ char sm_raw[];
    const int tid  = threadIdx.x;
    const int wid  = tid >> 5;
    const int lane = tid & 31;
    const uint32_t sbase = smem_u32(sm_raw);

    const long m0 = (long)blockIdx.y * 128;
    const int  n0 = blockIdx.x * 128;
    const int  wm = (wid & 3) * 32;     // warp m offset within tile
    const int  wn = (wid >> 2) * 64;    // warp n offset within tile

    const char* tpA  = (const char*)(g_ehi + m0 * GK);
    const char* tpAl = (const char*)(g_elo + m0 * GK);
    const char* tpB  = (const char*)(g_whi + (size_t)n0 * GK);
    const char* tpBl = (const char*)(g_wlo + (size_t)n0 * GK);

    float acc[2][8][4];
#pragma unroll
    for (int i = 0; i < 2; i++)
#pragma unroll
        for (int j = 0; j < 8; j++)
#pragma unroll
            for (int q = 0; q < 4; q++) acc[i][j][q] = 0.f;

    gemm_prefetch(sbase, 0, 0, tid, tpA, tpAl, tpB, tpBl);
    cp_commit();

    const uint32_t lrow = lane & 15;
    const uint32_t lcol = (lane >> 4) * 16;

    for (int kc = 0; kc < NKC; kc++) {
        const int cur = kc & 1;
        if (kc + 1 < NKC) {
            gemm_prefetch(sbase, cur ^ 1, kc + 1, tid, tpA, tpAl, tpB, tpBl);
            cp_commit();
            asm volatile("cp.async.wait_group 1;" ::: "memory");
        } else {
            asm volatile("cp.async.wait_group 0;" ::: "memory");
        }
        __syncthreads();

        const uint32_t aHi = sbase + cur * STAGEB;
        const uint32_t aLo = aHi + TILEB;
        const uint32_t bHi = aHi + 2 * TILEB;
        const uint32_t bLo = aHi + 3 * TILEB;

#pragma unroll
        for (int ks = 0; ks < 2; ks++) {
            const uint32_t coff = ks * 32 + lcol;
            uint32_t ah[2][4], al[2][4], bh[4][4], bl[4][4];
#pragma unroll
            for (int mt = 0; mt < 2; mt++) {
                uint32_t r = (wm + mt * 16 + lrow) * AROWB + coff;
                ldmatrix_x4(ah[mt], aHi + r);
                ldmatrix_x4(al[mt], aLo + r);
            }
#pragma unroll
            for (int g = 0; g < 4; g++) {
                uint32_t r = (wn + g * 16 + lrow) * AROWB + coff;
                ldmatrix_x4(bh[g], bHi + r);
                ldmatrix_x4(bl[g], bLo + r);
            }
#pragma unroll
            for (int mt = 0; mt < 2; mt++) {
#pragma unroll
                for (int g = 0; g < 4; g++) {
                    float* c0 = acc[mt][2 * g];
                    float* c1 = acc[mt][2 * g + 1];
                    mma_bf16(c0, ah[mt], bh[g][0], bh[g][2]);
                    mma_bf16(c1, ah[mt], bh[g][1], bh[g][3]);
                    mma_bf16(c0, ah[mt], bl[g][0], bl[g][2]);
                    mma_bf16(c1, ah[mt], bl[g][1], bl[g][3]);
                    mma_bf16(c0, al[mt], bh[g][0], bh[g][2]);
                    mma_bf16(c1, al[mt], bh[g][1], bh[g][3]);
                }
            }
        }
        __syncthreads();
    }

    // ---- epilogue: stage D in smem, then coalesced global write ----
    float* sD = (float*)sm_raw;   // 128 x 132
#pragma unroll
    for (int mt = 0; mt < 2; mt++) {
#pragma unroll
        for (int nt = 0; nt < 8; nt++) {
            int ml = wm + mt * 16 + (lane >> 2);
            int nl = wn + nt * 8 + (lane & 3) * 2;
            float2 v0 = make_float2(acc[mt][nt][0], acc[mt][nt][1]);
            float2 v1 = make_float2(acc[mt][nt][2], acc[mt][nt][3]);
            *(float2*)&sD[ml * 132 + nl]       = v0;
            *(float2*)&sD[(ml + 8) * 132 + nl] = v1;
        }
    }
    __syncthreads();

    for (int i = tid; i < 128 * 128; i += 256) {
        int mm = i >> 7;
        int nn = i & 127;
        int ng = n0 + nn;
        float c = sD[mm * 132 + nn];
        long m = m0 + mm;
        if (ng < 1024) {
            g_a[m * EB + ng] = tanhf(c + ba[ng]);
        } else if (ng < 2048) {
            g_b[m * EB + (ng - 1024)] = c + bb[ng - 1024];
        } else if (ng < 2112) {
            g_dx[m * DH + (ng - 2048)] = c + bd[ng - 2048];
        }
    }
}

// ---------------- kernel 2: linear recurrence scan ----------------
__global__ void __launch_bounds__(64)
scan_kernel()
{
    const int bh = blockIdx.x;
    const int d  = threadIdx.x;
    const int b  = bh >> 4;
    const int h  = bh & 15;
    size_t base = (size_t)b * LL * EB + (size_t)h * DH + d;
    float hv = 0.f;
#pragma unroll 8
    for (int l = 0; l < LL; l++) {
        size_t idx = base + (size_t)l * EB;
        float av = g_a[idx];
        float bv = g_b[idx];
        hv = fmaf(av, hv, bv);
        g_hs[idx] = hv;
    }
}

// ---------------- kernel 3: fused per-token epilogue (chunked weights) ----------------
// 32 tokens per block, 256 threads. smem = max(PhaseA, PhaseB) = 16896 floats.
#define HS_STRIDE 68
#define G_STRIDE  264
#define POST_FLOATS (4096 + HS_STRIDE*32 + G_STRIDE*32 + HS_STRIDE*32)  // 16896
#define POST_BYTES  (POST_FLOATS * 4)

__device__ __forceinline__ float grp8_sum(float v) {
    v += __shfl_xor_sync(0xffffffffu, v, 1);
    v += __shfl_xor_sync(0xffffffffu, v, 2);
    v += __shfl_xor_sync(0xffffffffu, v, 4);
    return v;
}

__global__ void __launch_bounds__(256)
post_kernel(const float* __restrict__ Wc,  const float* __restrict__ bc,
            const float* __restrict__ head_w,
            const float* __restrict__ hn_g, const float* __restrict__ hn_b,
            const float* __restrict__ W1,  const float* __restrict__ b1,
            const float* __restrict__ W2,  const float* __restrict__ b2,
            const float* __restrict__ Wp,  const float* __restrict__ bp,
            const float* __restrict__ ng,  const float* __restrict__ nb,
            float* __restrict__ out)
{
    extern __shared__ float sm[];
    const int tid = threadIdx.x;
    const int tt  = tid >> 3;     // token 0..31
    const int eg  = tid & 7;
    const int e0  = eg * 8;
    const long token0 = (long)blockIdx.x * 32;
    const long tok = token0 + tt;

    // ---- Phase A: sWc = sm[0:4096), sHs = sm[4096 : 4096+2176) ----
    float* sWc = sm;
    float* sHs = sm + 4096;

    float dxv[8], acc[8];
#pragma unroll
    for (int k = 0; k < 8; k++) {
        dxv[k] = g_dx[tok * DH + e0 + k];
        acc[k] = dxv[k];
    }

    for (int h = 0; h < NH; h++) {
        __syncthreads();
#pragma unroll
        for (int i = 0; i < 16; i++)
            sWc[tid + i * 256] = Wc[(size_t)h * 4096 + tid + i * 256];
#pragma unroll
        for (int i = 0; i < 8; i++) {
            int idx = tid + i * 256;
            int t = idx >> 6, d = idx & 63;
            sHs[t * HS_STRIDE + d] = g_hs[(token0 + t) * (long)EB + h * DH + d];
        }
        __syncthreads();

        float o[8];
#pragma unroll
        for (int k = 0; k < 8; k++) o[k] = bc[h * DH + e0 + k] + dxv[k];
#pragma unroll 8
        for (int d = 0; d < 64; d++) {
            float hv = sHs[tt * HS_STRIDE + d];
            float4 w0 = *(const float4*)&sWc[d * 64 + e0];
            float4 w1 = *(const float4*)&sWc[d * 64 + e0 + 4];
            o[0] = fmaf(hv, w0.x, o[0]); o[1] = fmaf(hv, w0.y, o[1]);
            o[2] = fmaf(hv, w0.z, o[2]); o[3] = fmaf(hv, w0.w, o[3]);
            o[4] = fmaf(hv, w1.x, o[4]); o[5] = fmaf(hv, w1.y, o[5]);
            o[6] = fmaf(hv, w1.z, o[6]); o[7] = fmaf(hv, w1.w, o[7]);
        }
        float s1 = 0.f, s2 = 0.f;
#pragma unroll
        for (int k = 0; k < 8; k++) { s1 += o[k]; s2 += o[k] * o[k]; }
        s1 = grp8_sum(s1); s2 = grp8_sum(s2);
        float mean = s1 * (1.f / 64.f);
        float var  = s2 * (1.f / 64.f) - mean * mean;
        float rstd = rsqrtf(var + 1e-5f);
        float hw = head_w[h];
#pragma unroll
        for (int k = 0; k < 8; k++) {
            float lnv = (o[k] - mean) * rstd * hn_g[h * DH + e0 + k] + hn_b[h * DH + e0 + k];
            acc[k] = fmaf(hw, lnv, acc[k]);
        }
    }

    float u[8];
    {
        float s1 = 0.f, s2 = 0.f;
#pragma unroll
        for (int k = 0; k < 8; k++) {
            acc[k] *= (1.f / (float)NH);
            s1 += acc[k]; s2 += acc[k] * acc[k];
        }
        s1 = grp8_sum(s1); s2 = grp8_sum(s2);
        float mean = s1 * (1.f / 64.f);
        float var  = s2 * (1.f / 64.f) - mean * mean;
        float rstd = rsqrtf(var + 1e-5f);
#pragma unroll
        for (int k = 0; k < 8; k++)
            u[k] = acc[k] + (acc[k] - mean) * rstd * ng[e0 + k] + nb[e0 + k];
    }

    __syncthreads();

    // ---- Phase B: sChunk = sm[0:4096), sU = +4096, sG = +6272, sHo = +14720 ----
    float* sChunk = sm;
    float* sU  = sm + 4096;
    float* sG  = sm + 4096 + 32 * HS_STRIDE;
    float* sHo = sG + 32 * G_STRIDE;

#pragma unroll
    for (int k = 0; k < 8; k++) sU[tt * HS_STRIDE + e0 + k] = u[k];

    // FFN mid, W1 chunked over j (4 chunks of 64)
    for (int jc = 0; jc < 4; jc++) {
        __syncthreads();
#pragma unroll
        for (int i = 0; i < 16; i++) {
            int idx = tid + i * 256;            // 0..4095
            int d = idx >> 6, jj = idx & 63;
            sChunk[idx] = W1[d * 256 + jc * 64 + jj];
        }
        __syncthreads();
#pragma unroll
        for (int kk = 0; kk < 8; kk++) {
            int jl = eg + 8 * kk;               // 0..63
            int j  = jc * 64 + jl;
            float m = b1[j];
#pragma unroll 8
            for (int d = 0; d < 64; d++)
                m = fmaf(sU[tt * HS_STRIDE + d], sChunk[d * 64 + jl], m);
            float g = 0.5f * m * (1.f + erff(m * 0.70710678118654752f));
            sG[tt * G_STRIDE + j] = g;
        }
    }

    // FFN out, W2 chunked over j (4 chunks of 64)
    float o2[8];
#pragma unroll
    for (int k = 0; k < 8; k++) o2[k] = b2[e0 + k];
    for (int jc = 0; jc < 4; jc++) {
        __syncthreads();
#pragma unroll
        for (int i = 0; i < 16; i++) {
            int idx = tid + i * 256;            // jj*64 + e
            int jj = idx >> 6, e = idx & 63;
            sChunk[idx] = W2[(jc * 64 + jj) * 64 + e];
        }
        __syncthreads();
#pragma unroll 8
        for (int jj = 0; jj < 64; jj++) {
            float gv = sG[tt * G_STRIDE + jc * 64 + jj];
            float4 w0 = *(const float4*)&sChunk[jj * 64 + e0];
            float4 w1 = *(const float4*)&sChunk[jj * 64 + e0 + 4];
            o2[0] = fmaf(gv, w0.x, o2[0]); o2[1] = fmaf(gv, w0.y, o2[1]);
            o2[2] = fmaf(gv, w0.z, o2[2]); o2[3] = fmaf(gv, w0.w, o2[3]);
            o2[4] = fmaf(gv, w1.x, o2[4]); o2[5] = fmaf(gv, w1.y, o2[5]);
            o2[6] = fmaf(gv, w1.z, o2[6]); o2[7] = fmaf(gv, w1.w, o2[7]);
        }
    }

#pragma unroll
    for (int k = 0; k < 8; k++)
        sHo[tt * HS_STRIDE + e0 + k] = u[k] + o2[k];

    // final projection, Wp chunked over d (2 chunks of 32)
    float fo[8];
#pragma unroll
    for (int k = 0; k < 8; k++) fo[k] = bp[e0 + k];
    for (int dc = 0; dc < 2; dc++) {
        __syncthreads();
#pragma unroll
        for (int i = 0; i < 8; i++) {
            int idx = tid + i * 256;            // 0..2047 = d*64+e
            int d = idx >> 6, e = idx & 63;
            sChunk[idx] = Wp[(dc * 32 + d) * 64 + e];
        }
        __syncthreads();
#pragma unroll 8
        for (int d = 0; d < 32; d++) {
            float hv = sHo[tt * HS_STRIDE + dc * 32 + d];
            float4 w0 = *(const float4*)&sChunk[d * 64 + e0];
            float4 w1 = *(const float4*)&sChunk[d * 64 + e0 + 4];
            fo[0] = fmaf(hv, w0.x, fo[0]); fo[1] = fmaf(hv, w0.y, fo[1]);
            fo[2] = fmaf(hv, w0.z, fo[2]); fo[3] = fmaf(hv, w0.w, fo[3]);
            fo[4] = fmaf(hv, w1.x, fo[4]); fo[5] = fmaf(hv, w1.y, fo[5]);
            fo[6] = fmaf(hv, w1.z, fo[6]); fo[7] = fmaf(hv, w1.w, fo[7]);
        }
    }
#pragma unroll
    for (int k = 0; k < 8; k++)
        out[tok * DH + e0 + k] = fo[k];
}

// ---------------- launch ----------------
extern "C" void kernel_launch(void* const* d_in, const int* in_sizes, int n_in,
                              void* d_out, int out_size)
{
    const float* emb    = (const float*)d_in[0];
    const float* Wa     = (const float*)d_in[1];
    const float* ba     = (const float*)d_in[2];
    const float* Wb     = (const float*)d_in[3];
    const float* bb     = (const float*)d_in[4];
    const float* Wc     = (const float*)d_in[5];
    const float* bc     = (const float*)d_in[6];
    const float* head_w = (const float*)d_in[7];
    const float* hn_g   = (const float*)d_in[8];
    const float* hn_b   = (const float*)d_in[9];
    const float* Wd     = (const float*)d_in[10];
    const float* bd     = (const float*)d_in[11];
    const float* W1     = (const float*)d_in[12];
    const float* b1     = (const float*)d_in[13];
    const float* W2     = (const float*)d_in[14];
    const float* b2     = (const float*)d_in[15];
    const float* Wp     = (const float*)d_in[16];
    const float* bp     = (const float*)d_in[17];
    const float* ng     = (const float*)d_in[18];
    const float* nb     = (const float*)d_in[19];
    float* out = (float*)d_out;

    cudaFuncSetAttribute(gemm_tc_kernel, cudaFuncAttributeMaxDynamicSharedMemorySize, GEMM_SMEM);
    cudaFuncSetAttribute(post_kernel, cudaFuncAttributeMaxDynamicSharedMemorySize, POST_BYTES);

    conv_emb_kernel<<<(int)((size_t)MT * GK / 4 / 256), 256>>>(emb);
    pack_w_kernel<<<(int)(((size_t)GNP * GK + 255) / 256), 256>>>(Wa, Wb, Wd);

    dim3 ggrid(GNP / 128, MT / 128);
    gemm_tc_kernel<<<ggrid, 256, GEMM_SMEM>>>(ba, bb, bd);

    scan_kernel<<<BB * NH, 64>>>();

    post_kernel<<<MT / 32, 256, POST_BYTES>>>(Wc, bc, head_w, hn_g, hn_b,
                                              W1, b1, W2, b2, Wp, bp, ng, nb, out);
}

// round 5
// speedup vs baseline: 3.0049x; 2.2269x over previous
#include <cuda_runtime.h>
#include <cuda_bf16.h>
#include <math.h>
#include <stdint.h>

// Problem constants
#define EB 1024     // embed dim
#define DH 64       // head dim
#define NH 16       // heads
#define BB 8
#define LL 4096
#define MT (BB*LL)          // 32768 tokens
#define GN (2*EB + DH)      // 2112 real columns  [a | b | dx]
#define GNP 2176            // padded to 17 tiles of 128
#define GK EB

// ---------------- scratch ----------------
__device__ float g_a [ (size_t)MT * EB ];   // [B,L,H,D] tanh gate
__device__ float g_b [ (size_t)MT * EB ];   // [B,L,H,D] additive gate
__device__ float g_hs[ (size_t)MT * EB ];   // [B,L,H,D] scan output
__device__ float g_dx[ (size_t)MT * DH ];   // [B,L,D]
__device__ float g_wt[ (size_t)GNP * GK ];  // packed weights [n][k], tf32-rounded

// chunked-scan intermediates: [BH=128][CH=32][D=64]
#define SCH 32
#define SCL (LL / SCH)      // 128
__device__ float g_cp[128 * SCH * 64];
__device__ float g_cq[128 * SCH * 64];
__device__ float g_h0[128 * SCH * 64];

// ---------------- helpers ----------------
__device__ __forceinline__ uint32_t smem_u32(const void* p) {
    uint32_t r;
    asm("{ .reg .u64 t; cvta.to.shared.u64 t, %1; cvt.u32.u64 %0, t; }" : "=r"(r) : "l"(p));
    return r;
}
__device__ __forceinline__ void cp_async16(uint32_t dst, const void* src) {
    asm volatile("cp.async.cg.shared.global [%0], [%1], 16;" :: "r"(dst), "l"(src) : "memory");
}
__device__ __forceinline__ void cp_commit() {
    asm volatile("cp.async.commit_group;" ::: "memory");
}
__device__ __forceinline__ uint32_t tf32u(float x) {
    uint32_t u;
    asm("cvt.rna.tf32.f32 %0, %1;" : "=r"(u) : "f"(x));
    return u;
}
__device__ __forceinline__ void mma_tf32(float* c,
                                         uint32_t a0, uint32_t a1, uint32_t a2, uint32_t a3,
                                         uint32_t b0, uint32_t b1) {
    asm volatile(
        "mma.sync.aligned.m16n8k8.row.col.f32.tf32.tf32.f32 "
        "{%0,%1,%2,%3}, {%4,%5,%6,%7}, {%8,%9}, {%0,%1,%2,%3};"
        : "+f"(c[0]), "+f"(c[1]), "+f"(c[2]), "+f"(c[3])
        : "r"(a0), "r"(a1), "r"(a2), "r"(a3), "r"(b0), "r"(b1));
}

// ---------------- kernel: pack weights [n][k] K-major, tf32-rounded ----------------
__global__ void pack_w_kernel(const float* __restrict__ Wa,
                              const float* __restrict__ Wb,
                              const float* __restrict__ Wd)
{
    size_t idx = (size_t)blockIdx.x * 256 + threadIdx.x;
    if (idx >= (size_t)GNP * GK) return;
    int n = (int)(idx >> 10);
    int k = (int)(idx & 1023);
    float v = 0.f;
    if (n < 1024) {
        v = Wa[(size_t)(n >> 6) * (EB * DH) + (size_t)k * DH + (n & 63)];
    } else if (n < 2048) {
        int n2 = n - 1024;
        v = Wb[(size_t)(n2 >> 6) * (EB * DH) + (size_t)k * DH + (n2 & 63)];
    } else if (n < 2112) {
        v = Wd[(size_t)k * DH + (n - 2048)];
    }
    g_wt[idx] = __uint_as_float(tf32u(v));
}

// ---------------- kernel: TF32 gates GEMM ----------------
// C[M=32768, N=2176] = emb[M,K=1024] @ W^T[N,K], single tf32 pass.
// CTA tile 128x128, 8 warps of 32x64, K-chunk 32, cp.async double-buffer.
// ROWB = 192 bytes: 16B-aligned row starts (cp.async/LDS.128 legal) and
// 48-word row shift -> quarter-warp rows cover words 0-15/16-31: conflict-free.
#define KC 32
#define NKC (GK / KC)          // 32
#define ROWB 192               // 128 data + 64 pad
#define TILEB (128 * ROWB)     // 24576
#define STAGEB (2 * TILEB)     // A + B = 49152
#define GEMM_SMEM (2 * STAGEB) // 98304

__global__ void __launch_bounds__(256)
gemm_tf32_kernel(const float* __restrict__ emb,
                 const float* __restrict__ ba,
                 const float* __restrict__ bb,
                 const float* __restrict__ bd)
{
    extern __shared__ char sm_raw[];
    const int tid  = threadIdx.x;
    const int wid  = tid >> 5;
    const int lane = tid & 31;
    const uint32_t sbase = smem_u32(sm_raw);

    const long m0 = (long)blockIdx.y * 128;
    const int  n0 = blockIdx.x * 128;
    const int  wm = (wid & 3) * 32;
    const int  wn = (wid >> 2) * 64;

    const char* Ag = (const char*)(emb  + (size_t)m0 * GK);
    const char* Bg = (const char*)(g_wt + (size_t)n0 * GK);

    float acc[2][8][4];
#pragma unroll
    for (int i = 0; i < 2; i++)
#pragma unroll
        for (int j = 0; j < 8; j++)
#pragma unroll
            for (int q = 0; q < 4; q++) acc[i][j][q] = 0.f;

    // prologue prefetch (kc = 0)
#pragma unroll
    for (int j = 0; j < 4; j++) {
        int id  = tid + j * 256;         // 0..1023
        int row = id >> 3;
        int c   = (id & 7) * 16;
        cp_async16(sbase + row * ROWB + c,         Ag + (size_t)row * 4096 + c);
        cp_async16(sbase + TILEB + row * ROWB + c, Bg + (size_t)row * 4096 + c);
    }
    cp_commit();

    const int lrow4 = lane >> 2;         // 0..7
    const int lco   = (lane & 3) * 16;   // byte offset of this thread's 4 k-values

    for (int kc = 0; kc < NKC; kc++) {
        const int cur = kc & 1;
        if (kc + 1 < NKC) {
            const size_t kb = (size_t)(kc + 1) * 128;   // byte offset in K
            const uint32_t sst = sbase + (cur ^ 1) * STAGEB;
#pragma unroll
            for (int j = 0; j < 4; j++) {
                int id  = tid + j * 256;
                int row = id >> 3;
                int c   = (id & 7) * 16;
                cp_async16(sst + row * ROWB + c,         Ag + (size_t)row * 4096 + kb + c);
                cp_async16(sst + TILEB + row * ROWB + c, Bg + (size_t)row * 4096 + kb + c);
            }
            cp_commit();
            asm volatile("cp.async.wait_group 1;" ::: "memory");
        } else {
            asm volatile("cp.async.wait_group 0;" ::: "memory");
        }
        __syncthreads();

        const char* sA = sm_raw + cur * STAGEB;
        const char* sB = sA + TILEB;

#pragma unroll
        for (int k16 = 0; k16 < 2; k16++) {
            const int koff = k16 * 64 + lco;
            // A fragments: raw fp32 -> tf32 round in-register
            uint32_t aw[2][2][4];
#pragma unroll
            for (int mt = 0; mt < 2; mt++) {
#pragma unroll
                for (int hh = 0; hh < 2; hh++) {
                    float4 v = *(const float4*)(sA + (wm + mt * 16 + hh * 8 + lrow4) * ROWB + koff);
                    aw[mt][hh][0] = tf32u(v.x);
                    aw[mt][hh][1] = tf32u(v.y);
                    aw[mt][hh][2] = tf32u(v.z);
                    aw[mt][hh][3] = tf32u(v.w);
                }
            }
#pragma unroll
            for (int g = 0; g < 8; g++) {
                float4 bv = *(const float4*)(sB + (wn + g * 8 + lrow4) * ROWB + koff);
                uint32_t b0 = __float_as_uint(bv.x);
                uint32_t b1 = __float_as_uint(bv.y);
                uint32_t b2 = __float_as_uint(bv.z);
                uint32_t b3 = __float_as_uint(bv.w);
                // identical lane-local K-permutation on A and B: exact sum over k
                mma_tf32(acc[0][g], aw[0][0][0], aw[0][1][0], aw[0][0][1], aw[0][1][1], b0, b1);
                mma_tf32(acc[0][g], aw[0][0][2], aw[0][1][2], aw[0][0][3], aw[0][1][3], b2, b3);
                mma_tf32(acc[1][g], aw[1][0][0], aw[1][1][0], aw[1][0][1], aw[1][1][1], b0, b1);
                mma_tf32(acc[1][g], aw[1][0][2], aw[1][1][2], aw[1][0][3], aw[1][1][3], b2, b3);
            }
        }
        __syncthreads();
    }

    // ---- epilogue: stage D in smem, then coalesced global write ----
    float* sD = (float*)sm_raw;   // 128 x 132 = 67584 B <= GEMM_SMEM
#pragma unroll
    for (int mt = 0; mt < 2; mt++) {
#pragma unroll
        for (int g = 0; g < 8; g++) {
            int ml = wm + mt * 16 + (lane >> 2);
            int nl = wn + g * 8 + (lane & 3) * 2;
            *(float2*)&sD[ml * 132 + nl]       = make_float2(acc[mt][g][0], acc[mt][g][1]);
            *(float2*)&sD[(ml + 8) * 132 + nl] = make_float2(acc[mt][g][2], acc[mt][g][3]);
        }
    }
    __syncthreads();

    for (int i = tid; i < 128 * 128; i += 256) {
        int mm = i >> 7;
        int nn = i & 127;
        int ng = n0 + nn;
        float c = sD[mm * 132 + nn];
        long m = m0 + mm;
        if (ng < 1024) {
            g_a[m * EB + ng] = tanhf(c + ba[ng]);
        } else if (ng < 2048) {
            g_b[m * EB + (ng - 1024)] = c + bb[ng - 1024];
        } else if (ng < 2112) {
            g_dx[m * DH + (ng - 2048)] = c + bd[ng - 2048];
        }
    }
}

// ---------------- chunked linear-recurrence scan (3 phases) ----------------
__global__ void __launch_bounds__(64)
scanA_kernel()
{
    const int bc = blockIdx.x;           // bh*32 + c
    const int bh = bc >> 5;
    const int c  = bc & 31;
    const int d  = threadIdx.x;
    const int b  = bh >> 4;
    const int h  = bh & 15;
    size_t base = ((size_t)b * LL + (size_t)c * SCL) * EB + h * DH + d;
    float P = 1.f, Q = 0.f;
#pragma unroll 8
    for (int l = 0; l < SCL; l++) {
        size_t idx = base + (size_t)l * EB;
        float av = g_a[idx];
        float bv = g_b[idx];
        Q = fmaf(av, Q, bv);
        P *= av;
    }
    g_cp[bc * 64 + d] = P;
    g_cq[bc * 64 + d] = Q;
}

__global__ void __launch_bounds__(64)
scanB_kernel()
{
    const int bh = blockIdx.x;
    const int d  = threadIdx.x;
    float hv = 0.f;
#pragma unroll
    for (int c = 0; c < SCH; c++) {
        int i = (bh * SCH + c) * 64 + d;
        g_h0[i] = hv;
        hv = fmaf(g_cp[i], hv, g_cq[i]);
    }
}

__global__ void __launch_bounds__(64)
scanC_kernel()
{
    const int bc = blockIdx.x;
    const int bh = bc >> 5;
    const int c  = bc & 31;
    const int d  = threadIdx.x;
    const int b  = bh >> 4;
    const int h  = bh & 15;
    size_t base = ((size_t)b * LL + (size_t)c * SCL) * EB + h * DH + d;
    float hv = g_h0[bc * 64 + d];
#pragma unroll 8
    for (int l = 0; l < SCL; l++) {
        size_t idx = base + (size_t)l * EB;
        float av = g_a[idx];
        float bv = g_b[idx];
        hv = fmaf(av, hv, bv);
        g_hs[idx] = hv;
    }
}

// ---------------- kernel 3: fused per-token epilogue (chunked weights) ----------------
#define HS_STRIDE 68
#define G_STRIDE  264
#define POST_FLOATS (4096 + HS_STRIDE*32 + G_STRIDE*32 + HS_STRIDE*32)  // 16896
#define POST_BYTES  (POST_FLOATS * 4)

__device__ __forceinline__ float grp8_sum(float v) {
    v += __shfl_xor_sync(0xffffffffu, v, 1);
    v += __shfl_xor_sync(0xffffffffu, v, 2);
    v += __shfl_xor_sync(0xffffffffu, v, 4);
    return v;
}

__global__ void __launch_bounds__(256)
post_kernel(const float* __restrict__ Wc,  const float* __restrict__ bc,
            const float* __restrict__ head_w,
            const float* __restrict__ hn_g, const float* __restrict__ hn_b,
            const float* __restrict__ W1,  const float* __restrict__ b1,
            const float* __restrict__ W2,  const float* __restrict__ b2,
            const float* __restrict__ Wp,  const float* __restrict__ bp,
            const float* __restrict__ ng,  const float* __restrict__ nb,
            float* __restrict__ out)
{
    extern __shared__ float sm[];
    const int tid = threadIdx.x;
    const int tt  = tid >> 3;     // token 0..31
    const int eg  = tid & 7;
    const int e0  = eg * 8;
    const long token0 = (long)blockIdx.x * 32;
    const long tok = token0 + tt;

    float* sWc = sm;
    float* sHs = sm + 4096;

    float dxv[8], acc[8];
#pragma unroll
    for (int k = 0; k < 8; k++) {
        dxv[k] = g_dx[tok * DH + e0 + k];
        acc[k] = dxv[k];
    }

    for (int h = 0; h < NH; h++) {
        __syncthreads();
#pragma unroll
        for (int i = 0; i < 16; i++)
            sWc[tid + i * 256] = Wc[(size_t)h * 4096 + tid + i * 256];
#pragma unroll
        for (int i = 0; i < 8; i++) {
            int idx = tid + i * 256;
            int t = idx >> 6, d = idx & 63;
            sHs[t * HS_STRIDE + d] = g_hs[(token0 + t) * (long)EB + h * DH + d];
        }
        __syncthreads();

        float o[8];
#pragma unroll
        for (int k = 0; k < 8; k++) o[k] = bc[h * DH + e0 + k] + dxv[k];
#pragma unroll 8
        for (int d = 0; d < 64; d++) {
            float hv = sHs[tt * HS_STRIDE + d];
            float4 w0 = *(const float4*)&sWc[d * 64 + e0];
            float4 w1 = *(const float4*)&sWc[d * 64 + e0 + 4];
            o[0] = fmaf(hv, w0.x, o[0]); o[1] = fmaf(hv, w0.y, o[1]);
            o[2] = fmaf(hv, w0.z, o[2]); o[3] = fmaf(hv, w0.w, o[3]);
            o[4] = fmaf(hv, w1.x, o[4]); o[5] = fmaf(hv, w1.y, o[5]);
            o[6] = fmaf(hv, w1.z, o[6]); o[7] = fmaf(hv, w1.w, o[7]);
        }
        float s1 = 0.f, s2 = 0.f;
#pragma unroll
        for (int k = 0; k < 8; k++) { s1 += o[k]; s2 += o[k] * o[k]; }
        s1 = grp8_sum(s1); s2 = grp8_sum(s2);
        float mean = s1 * (1.f / 64.f);
        float var  = s2 * (1.f / 64.f) - mean * mean;
        float rstd = rsqrtf(var + 1e-5f);
        float hw = head_w[h];
#pragma unroll
        for (int k = 0; k < 8; k++) {
            float lnv = (o[k] - mean) * rstd * hn_g[h * DH + e0 + k] + hn_b[h * DH + e0 + k];
            acc[k] = fmaf(hw, lnv, acc[k]);
        }
    }

    float u[8];
    {
        float s1 = 0.f, s2 = 0.f;
#pragma unroll
        for (int k = 0; k < 8; k++) {
            acc[k] *= (1.f / (float)NH);
            s1 += acc[k]; s2 += acc[k] * acc[k];
        }
        s1 = grp8_sum(s1); s2 = grp8_sum(s2);
        float mean = s1 * (1.f / 64.f);
        float var  = s2 * (1.f / 64.f) - mean * mean;
        float rstd = rsqrtf(var + 1e-5f);
#pragma unroll
        for (int k = 0; k < 8; k++)
            u[k] = acc[k] + (acc[k] - mean) * rstd * ng[e0 + k] + nb[e0 + k];
    }

    __syncthreads();

    float* sChunk = sm;
    float* sU  = sm + 4096;
    float* sG  = sm + 4096 + 32 * HS_STRIDE;
    float* sHo = sG + 32 * G_STRIDE;

#pragma unroll
    for (int k = 0; k < 8; k++) sU[tt * HS_STRIDE + e0 + k] = u[k];

    for (int jc = 0; jc < 4; jc++) {
        __syncthreads();
#pragma unroll
        for (int i = 0; i < 16; i++) {
            int idx = tid + i * 256;
            int d = idx >> 6, jj = idx & 63;
            sChunk[idx] = W1[d * 256 + jc * 64 + jj];
        }
        __syncthreads();
#pragma unroll
        for (int kk = 0; kk < 8; kk++) {
            int jl = eg + 8 * kk;
            int j  = jc * 64 + jl;
            float m = b1[j];
#pragma unroll 8
            for (int d = 0; d < 64; d++)
                m = fmaf(sU[tt * HS_STRIDE + d], sChunk[d * 64 + jl], m);
            float g = 0.5f * m * (1.f + erff(m * 0.70710678118654752f));
            sG[tt * G_STRIDE + j] = g;
        }
    }

    float o2[8];
#pragma unroll
    for (int k = 0; k < 8; k++) o2[k] = b2[e0 + k];
    for (int jc = 0; jc < 4; jc++) {
        __syncthreads();
#pragma unroll
        for (int i = 0; i < 16; i++) {
            int idx = tid + i * 256;
            int jj = idx >> 6, e = idx & 63;
            sChunk[idx] = W2[(jc * 64 + jj) * 64 + e];
        }
        __syncthreads();
#pragma unroll 8
        for (int jj = 0; jj < 64; jj++) {
            float gv = sG[tt * G_STRIDE + jc * 64 + jj];
            float4 w0 = *(const float4*)&sChunk[jj * 64 + e0];
            float4 w1 = *(const float4*)&sChunk[jj * 64 + e0 + 4];
            o2[0] = fmaf(gv, w0.x, o2[0]); o2[1] = fmaf(gv, w0.y, o2[1]);
            o2[2] = fmaf(gv, w0.z, o2[2]); o2[3] = fmaf(gv, w0.w, o2[3]);
            o2[4] = fmaf(gv, w1.x, o2[4]); o2[5] = fmaf(gv, w1.y, o2[5]);
            o2[6] = fmaf(gv, w1.z, o2[6]); o2[7] = fmaf(gv, w1.w, o2[7]);
        }
    }

#pragma unroll
    for (int k = 0; k < 8; k++)
        sHo[tt * HS_STRIDE + e0 + k] = u[k] + o2[k];

    float fo[8];
#pragma unroll
    for (int k = 0; k < 8; k++) fo[k] = bp[e0 + k];
    for (int dc = 0; dc < 2; dc++) {
        __syncthreads();
#pragma unroll
        for (int i = 0; i < 8; i++) {
            int idx = tid + i * 256;
            int d = idx >> 6, e = idx & 63;
            sChunk[idx] = Wp[(dc * 32 + d) * 64 + e];
        }
        __syncthreads();
#pragma unroll 8
        for (int d = 0; d < 32; d++) {
            float hv = sHo[tt * HS_STRIDE + dc * 32 + d];
            float4 w0 = *(const float4*)&sChunk[d * 64 + e0];
            float4 w1 = *(const float4*)&sChunk[d * 64 + e0 + 4];
            fo[0] = fmaf(hv, w0.x, fo[0]); fo[1] = fmaf(hv, w0.y, fo[1]);
            fo[2] = fmaf(hv, w0.z, fo[2]); fo[3] = fmaf(hv, w0.w, fo[3]);
            fo[4] = fmaf(hv, w1.x, fo[4]); fo[5] = fmaf(hv, w1.y, fo[5]);
            fo[6] = fmaf(hv, w1.z, fo[6]); fo[7] = fmaf(hv, w1.w, fo[7]);
        }
    }
#pragma unroll
    for (int k = 0; k < 8; k++)
        out[tok * DH + e0 + k] = fo[k];
}

// ---------------- launch ----------------
extern "C" void kernel_launch(void* const* d_in, const int* in_sizes, int n_in,
                              void* d_out, int out_size)
{
    const float* emb    = (const float*)d_in[0];
    const float* Wa     = (const float*)d_in[1];
    const float* ba     = (const float*)d_in[2];
    const float* Wb     = (const float*)d_in[3];
    const float* bb     = (const float*)d_in[4];
    const float* Wc     = (const float*)d_in[5];
    const float* bc     = (const float*)d_in[6];
    const float* head_w = (const float*)d_in[7];
    const float* hn_g   = (const float*)d_in[8];
    const float* hn_b   = (const float*)d_in[9];
    const float* Wd     = (const float*)d_in[10];
    const float* bd     = (const float*)d_in[11];
    const float* W1     = (const float*)d_in[12];
    const float* b1     = (const float*)d_in[13];
    const float* W2     = (const float*)d_in[14];
    const float* b2     = (const float*)d_in[15];
    const float* Wp     = (const float*)d_in[16];
    const float* bp     = (const float*)d_in[17];
    const float* ng     = (const float*)d_in[18];
    const float* nb     = (const float*)d_in[19];
    float* out = (float*)d_out;

    cudaFuncSetAttribute(gemm_tf32_kernel, cudaFuncAttributeMaxDynamicSharedMemorySize, GEMM_SMEM);
    cudaFuncSetAttribute(post_kernel, cudaFuncAttributeMaxDynamicSharedMemorySize, POST_BYTES);

    pack_w_kernel<<<(int)(((size_t)GNP * GK + 255) / 256), 256>>>(Wa, Wb, Wd);

    dim3 ggrid(GNP / 128, MT / 128);
    gemm_tf32_kernel<<<ggrid, 256, GEMM_SMEM>>>(emb, ba, bb, bd);

    scanA_kernel<<<128 * SCH, 64>>>();
    scanB_kernel<<<128, 64>>>();
    scanC_kernel<<<128 * SCH, 64>>>();

    post_kernel<<<MT / 32, 256, POST_BYTES>>>(Wc, bc, head_w, hn_g, hn_b,
                                              W1, b1, W2, b2, Wp, bp, ng, nb, out);
}

// round 6
// speedup vs baseline: 3.2804x; 1.0917x over previous
#include <cuda_runtime.h>
#include <cuda_bf16.h>
#include <math.h>
#include <stdint.h>

// Problem constants
#define EB 1024     // embed dim
#define DH 64       // head dim
#define NH 16       // heads
#define BB 8
#define LL 4096
#define MT (BB*LL)          // 32768 tokens
#define GN (2*EB + DH)      // 2112 real columns  [a | b | dx]
#define GNP 2176            // padded to 17 tiles of 128
#define GK EB

// ---------------- scratch ----------------
__device__ float g_a [ (size_t)MT * EB ];   // [B,L,H,D] tanh gate
__device__ float g_b [ (size_t)MT * EB ];   // [B,L,H,D] additive gate
__device__ float g_hs[ (size_t)MT * EB ];   // [B,L,H,D] scan output
__device__ float g_dx[ (size_t)MT * DH ];   // [B,L,D]
__device__ float g_wt[ (size_t)GNP * GK ];  // packed weights [n][k], tf32-rounded

// chunked-scan intermediates: [BH=128][CH=32][D=64]
#define SCH 32
#define SCL (LL / SCH)      // 128
__device__ float g_cp[128 * SCH * 64];
__device__ float g_cq[128 * SCH * 64];
__device__ float g_h0[128 * SCH * 64];

// ---------------- helpers ----------------
__device__ __forceinline__ uint32_t smem_u32(const void* p) {
    uint32_t r;
    asm("{ .reg .u64 t; cvta.to.shared.u64 t, %1; cvt.u32.u64 %0, t; }" : "=r"(r) : "l"(p));
    return r;
}
__device__ __forceinline__ void cp_async16(uint32_t dst, const void* src) {
    asm volatile("cp.async.cg.shared.global [%0], [%1], 16;" :: "r"(dst), "l"(src) : "memory");
}
__device__ __forceinline__ void cp_commit() {
    asm volatile("cp.async.commit_group;" ::: "memory");
}
__device__ __forceinline__ uint32_t tf32u(float x) {
    uint32_t u;
    asm("cvt.rna.tf32.f32 %0, %1;" : "=r"(u) : "f"(x));
    return u;
}
__device__ __forceinline__ void mma_tf32(float* c,
                                         uint32_t a0, uint32_t a1, uint32_t a2, uint32_t a3,
                                         uint32_t b0, uint32_t b1) {
    asm volatile(
        "mma.sync.aligned.m16n8k8.row.col.f32.tf32.tf32.f32 "
        "{%0,%1,%2,%3}, {%4,%5,%6,%7}, {%8,%9}, {%0,%1,%2,%3};"
        : "+f"(c[0]), "+f"(c[1]), "+f"(c[2]), "+f"(c[3])
        : "r"(a0), "r"(a1), "r"(a2), "r"(a3), "r"(b0), "r"(b1));
}

// ---------------- kernel: pack weights [n][k] K-major, tf32-rounded ----------------
__global__ void pack_w_kernel(const float* __restrict__ Wa,
                              const float* __restrict__ Wb,
                              const float* __restrict__ Wd)
{
    size_t idx = (size_t)blockIdx.x * 256 + threadIdx.x;
    if (idx >= (size_t)GNP * GK) return;
    int n = (int)(idx >> 10);
    int k = (int)(idx & 1023);
    float v = 0.f;
    if (n < 1024) {
        v = Wa[(size_t)(n >> 6) * (EB * DH) + (size_t)k * DH + (n & 63)];
    } else if (n < 2048) {
        int n2 = n - 1024;
        v = Wb[(size_t)(n2 >> 6) * (EB * DH) + (size_t)k * DH + (n2 & 63)];
    } else if (n < 2112) {
        v = Wd[(size_t)k * DH + (n - 2048)];
    }
    g_wt[idx] = __uint_as_float(tf32u(v));
}

// ---------------- kernel: TF32 gates GEMM ----------------
// C[M=32768, N=2176] = emb[M,K=1024] @ W^T[N,K], single tf32 pass.
// CTA tile 128x128, 8 warps of 32x64, K-chunk 32, cp.async double-buffer.
// Bank-conflict-free layout: ROWB=128, 16B chunks XOR-swizzled by row parity:
//   phys_chunk = chunk ^ ((row & 1) << 2)
// so each 8-lane LDS.128 phase (2 rows x 4 chunks) covers all 32 banks.
#define KC 32
#define NKC (GK / KC)          // 32
#define ROWB 128
#define TILEB (128 * ROWB)     // 16384
#define STAGEB (2 * TILEB)     // A + B = 32768
#define GEMM_SMEM 67584        // max(2*STAGEB=65536, sD 128*132*4=67584)

#define SWZ(row, chunk) ((uint32_t)((row) * ROWB + ((((chunk) ^ (((row) & 1) << 2))) << 4)))

__global__ void __launch_bounds__(256)
gemm_tf32_kernel(const float* __restrict__ emb,
                 const float* __restrict__ ba,
                 const float* __restrict__ bb,
                 const float* __restrict__ bd)
{
    extern __shared__ char sm_raw[];
    const int tid  = threadIdx.x;
    const int wid  = tid >> 5;
    const int lane = tid & 31;
    const uint32_t sbase = smem_u32(sm_raw);

    const long m0 = (long)blockIdx.y * 128;
    const int  n0 = blockIdx.x * 128;
    const int  wm = (wid & 3) * 32;
    const int  wn = (wid >> 2) * 64;

    const char* Ag = (const char*)(emb  + (size_t)m0 * GK);
    const char* Bg = (const char*)(g_wt + (size_t)n0 * GK);

    float acc[2][8][4];
#pragma unroll
    for (int i = 0; i < 2; i++)
#pragma unroll
        for (int j = 0; j < 8; j++)
#pragma unroll
            for (int q = 0; q < 4; q++) acc[i][j][q] = 0.f;

    // prologue prefetch (kc = 0)
#pragma unroll
    for (int j = 0; j < 4; j++) {
        int id  = tid + j * 256;         // 0..1023
        int row = id >> 3;
        int c   = id & 7;
        cp_async16(sbase + SWZ(row, c),         Ag + (size_t)row * 4096 + c * 16);
        cp_async16(sbase + TILEB + SWZ(row, c), Bg + (size_t)row * 4096 + c * 16);
    }
    cp_commit();

    const int lrow4 = lane >> 2;         // 0..7
    const int lch   = lane & 3;          // chunk within k16 half

    for (int kc = 0; kc < NKC; kc++) {
        const int cur = kc & 1;
        if (kc + 1 < NKC) {
            const size_t kb = (size_t)(kc + 1) * 128;   // byte offset in K
            const uint32_t sst = sbase + (cur ^ 1) * STAGEB;
#pragma unroll
            for (int j = 0; j < 4; j++) {
                int id  = tid + j * 256;
                int row = id >> 3;
                int c   = id & 7;
                cp_async16(sst + SWZ(row, c),         Ag + (size_t)row * 4096 + kb + c * 16);
                cp_async16(sst + TILEB + SWZ(row, c), Bg + (size_t)row * 4096 + kb + c * 16);
            }
            cp_commit();
            asm volatile("cp.async.wait_group 1;" ::: "memory");
        } else {
            asm volatile("cp.async.wait_group 0;" ::: "memory");
        }
        __syncthreads();

        const char* sA = sm_raw + cur * STAGEB;
        const char* sB = sA + TILEB;

#pragma unroll
        for (int k16 = 0; k16 < 2; k16++) {
            const int ch = k16 * 4 + lch;
            // A fragments: raw fp32 -> tf32 round in-register
            uint32_t aw[2][2][4];
#pragma unroll
            for (int mt = 0; mt < 2; mt++) {
#pragma unroll
                for (int hh = 0; hh < 2; hh++) {
                    int row = wm + mt * 16 + hh * 8 + lrow4;
                    float4 v = *(const float4*)(sA + SWZ(row, ch));
                    aw[mt][hh][0] = tf32u(v.x);
                    aw[mt][hh][1] = tf32u(v.y);
                    aw[mt][hh][2] = tf32u(v.z);
                    aw[mt][hh][3] = tf32u(v.w);
                }
            }
#pragma unroll
            for (int g = 0; g < 8; g++) {
                int row = wn + g * 8 + lrow4;
                float4 bv = *(const float4*)(sB + SWZ(row, ch));
                uint32_t b0 = __float_as_uint(bv.x);
                uint32_t b1 = __float_as_uint(bv.y);
                uint32_t b2 = __float_as_uint(bv.z);
                uint32_t b3 = __float_as_uint(bv.w);
                // identical lane-local K-permutation on A and B: exact sum over k
                mma_tf32(acc[0][g], aw[0][0][0], aw[0][1][0], aw[0][0][1], aw[0][1][1], b0, b1);
                mma_tf32(acc[0][g], aw[0][0][2], aw[0][1][2], aw[0][0][3], aw[0][1][3], b2, b3);
                mma_tf32(acc[1][g], aw[1][0][0], aw[1][1][0], aw[1][0][1], aw[1][1][1], b0, b1);
                mma_tf32(acc[1][g], aw[1][0][2], aw[1][1][2], aw[1][0][3], aw[1][1][3], b2, b3);
            }
        }
        __syncthreads();
    }

    // ---- epilogue: stage D in smem, then coalesced global write ----
    float* sD = (float*)sm_raw;   // 128 x 132
#pragma unroll
    for (int mt = 0; mt < 2; mt++) {
#pragma unroll
        for (int g = 0; g < 8; g++) {
            int ml = wm + mt * 16 + (lane >> 2);
            int nl = wn + g * 8 + (lane & 3) * 2;
            *(float2*)&sD[ml * 132 + nl]       = make_float2(acc[mt][g][0], acc[mt][g][1]);
            *(float2*)&sD[(ml + 8) * 132 + nl] = make_float2(acc[mt][g][2], acc[mt][g][3]);
        }
    }
    __syncthreads();

    for (int i = tid; i < 128 * 128; i += 256) {
        int mm = i >> 7;
        int nn = i & 127;
        int ng = n0 + nn;
        float c = sD[mm * 132 + nn];
        long m = m0 + mm;
        if (ng < 1024) {
            g_a[m * EB + ng] = tanhf(c + ba[ng]);
        } else if (ng < 2048) {
            g_b[m * EB + (ng - 1024)] = c + bb[ng - 1024];
        } else if (ng < 2112) {
            g_dx[m * DH + (ng - 2048)] = c + bd[ng - 2048];
        }
    }
}

// ---------------- chunked linear-recurrence scan (3 phases) ----------------
__global__ void __launch_bounds__(64)
scanA_kernel()
{
    const int bc = blockIdx.x;           // bh*32 + c
    const int bh = bc >> 5;
    const int c  = bc & 31;
    const int d  = threadIdx.x;
    const int b  = bh >> 4;
    const int h  = bh & 15;
    size_t base = ((size_t)b * LL + (size_t)c * SCL) * EB + h * DH + d;
    float P = 1.f, Q = 0.f;
#pragma unroll 8
    for (int l = 0; l < SCL; l++) {
        size_t idx = base + (size_t)l * EB;
        float av = g_a[idx];
        float bv = g_b[idx];
        Q = fmaf(av, Q, bv);
        P *= av;
    }
    g_cp[bc * 64 + d] = P;
    g_cq[bc * 64 + d] = Q;
}

__global__ void __launch_bounds__(64)
scanB_kernel()
{
    const int bh = blockIdx.x;
    const int d  = threadIdx.x;
    float hv = 0.f;
#pragma unroll
    for (int c = 0; c < SCH; c++) {
        int i = (bh * SCH + c) * 64 + d;
        g_h0[i] = hv;
        hv = fmaf(g_cp[i], hv, g_cq[i]);
    }
}

__global__ void __launch_bounds__(64)
scanC_kernel()
{
    const int bc = blockIdx.x;
    const int bh = bc >> 5;
    const int c  = bc & 31;
    const int d  = threadIdx.x;
    const int b  = bh >> 4;
    const int h  = bh & 15;
    size_t base = ((size_t)b * LL + (size_t)c * SCL) * EB + h * DH + d;
    float hv = g_h0[bc * 64 + d];
#pragma unroll 8
    for (int l = 0; l < SCL; l++) {
        size_t idx = base + (size_t)l * EB;
        float av = g_a[idx];
        float bv = g_b[idx];
        hv = fmaf(av, hv, bv);
        g_hs[idx] = hv;
    }
}

// ---------------- kernel 3: fused per-token epilogue ----------------
// Phase A double-buffered via cp.async: smem [Wc0|Wc1|hs0|hs1] = 12544 floats.
// Phase B overlays: 16896 floats total.
#define HS_STRIDE 68
#define G_STRIDE  264
#define POST_FLOATS (4096 + HS_STRIDE*32 + G_STRIDE*32 + HS_STRIDE*32)  // 16896
#define POST_BYTES  (POST_FLOATS * 4)

__device__ __forceinline__ float grp8_sum(float v) {
    v += __shfl_xor_sync(0xffffffffu, v, 1);
    v += __shfl_xor_sync(0xffffffffu, v, 2);
    v += __shfl_xor_sync(0xffffffffu, v, 4);
    return v;
}

__device__ __forceinline__ void post_prefetch(uint32_t swc, uint32_t shs,
                                              const float* __restrict__ Wc,
                                              int h, long token0, int tid)
{
    const char* wsrc = (const char*)(Wc + (size_t)h * 4096);
#pragma unroll
    for (int i = 0; i < 4; i++) {
        int idx = tid + i * 256;                 // 0..1023 16B chunks
        cp_async16(swc + idx * 16, wsrc + idx * 16);
    }
#pragma unroll
    for (int i = 0; i < 2; i++) {
        int idx = tid + i * 256;                 // 0..511
        int t = idx >> 4;                        // token 0..31
        int c = idx & 15;                        // 16B chunk within 64 floats
        const char* hsrc = (const char*)(g_hs + (token0 + t) * (size_t)EB + h * 64);
        cp_async16(shs + (uint32_t)(t * HS_STRIDE * 4 + c * 16), hsrc + c * 16);
    }
}

__global__ void __launch_bounds__(256)
post_kernel(const float* __restrict__ Wc,  const float* __restrict__ bc,
            const float* __restrict__ head_w,
            const float* __restrict__ hn_g, const float* __restrict__ hn_b,
            const float* __restrict__ W1,  const float* __restrict__ b1,
            const float* __restrict__ W2,  const float* __restrict__ b2,
            const float* __restrict__ Wp,  const float* __restrict__ bp,
            const float* __restrict__ ng,  const float* __restrict__ nb,
            float* __restrict__ out)
{
    extern __shared__ float sm[];
    const int tid = threadIdx.x;
    const int tt  = tid >> 3;     // token 0..31
    const int eg  = tid & 7;
    const int e0  = eg * 8;
    const long token0 = (long)blockIdx.x * 32;
    const long tok = token0 + tt;

    // Phase A buffers
    const uint32_t swc_u0 = smem_u32(sm);
    const uint32_t swc_u1 = smem_u32(sm + 4096);
    const uint32_t shs_u0 = smem_u32(sm + 8192);
    const uint32_t shs_u1 = smem_u32(sm + 8192 + 32 * HS_STRIDE);

    float dxv[8], acc[8];
#pragma unroll
    for (int k = 0; k < 8; k++) {
        dxv[k] = g_dx[tok * DH + e0 + k];
        acc[k] = dxv[k];
    }

    post_prefetch(swc_u0, shs_u0, Wc, 0, token0, tid);
    cp_commit();

    for (int h = 0; h < NH; h++) {
        const int cur = h & 1;
        if (h + 1 < NH) {
            post_prefetch(cur ? swc_u0 : swc_u1, cur ? shs_u0 : shs_u1, Wc, h + 1, token0, tid);
            cp_commit();
            asm volatile("cp.async.wait_group 1;" ::: "memory");
        } else {
            asm volatile("cp.async.wait_group 0;" ::: "memory");
        }
        __syncthreads();

        const float* sWc = sm + (cur ? 4096 : 0);
        const float* sHs = sm + 8192 + (cur ? 32 * HS_STRIDE : 0);

        float o[8];
#pragma unroll
        for (int k = 0; k < 8; k++) o[k] = bc[h * DH + e0 + k] + dxv[k];
#pragma unroll 8
        for (int d = 0; d < 64; d++) {
            float hv = sHs[tt * HS_STRIDE + d];
            float4 w0 = *(const float4*)&sWc[d * 64 + e0];
            float4 w1 = *(const float4*)&sWc[d * 64 + e0 + 4];
            o[0] = fmaf(hv, w0.x, o[0]); o[1] = fmaf(hv, w0.y, o[1]);
            o[2] = fmaf(hv, w0.z, o[2]); o[3] = fmaf(hv, w0.w, o[3]);
            o[4] = fmaf(hv, w1.x, o[4]); o[5] = fmaf(hv, w1.y, o[5]);
            o[6] = fmaf(hv, w1.z, o[6]); o[7] = fmaf(hv, w1.w, o[7]);
        }
        float s1 = 0.f, s2 = 0.f;
#pragma unroll
        for (int k = 0; k < 8; k++) { s1 += o[k]; s2 += o[k] * o[k]; }
        s1 = grp8_sum(s1); s2 = grp8_sum(s2);
        float mean = s1 * (1.f / 64.f);
        float var  = s2 * (1.f / 64.f) - mean * mean;
        float rstd = rsqrtf(var + 1e-5f);
        float hw = head_w[h];
#pragma unroll
        for (int k = 0; k < 8; k++) {
            float lnv = (o[k] - mean) * rstd * hn_g[h * DH + e0 + k] + hn_b[h * DH + e0 + k];
            acc[k] = fmaf(hw, lnv, acc[k]);
        }
        __syncthreads();
    }

    float u[8];
    {
        float s1 = 0.f, s2 = 0.f;
#pragma unroll
        for (int k = 0; k < 8; k++) {
            acc[k] *= (1.f / (float)NH);
            s1 += acc[k]; s2 += acc[k] * acc[k];
        }
        s1 = grp8_sum(s1); s2 = grp8_sum(s2);
        float mean = s1 * (1.f / 64.f);
        float var  = s2 * (1.f / 64.f) - mean * mean;
        float rstd = rsqrtf(var + 1e-5f);
#pragma unroll
        for (int k = 0; k < 8; k++)
            u[k] = acc[k] + (acc[k] - mean) * rstd * ng[e0 + k] + nb[e0 + k];
    }

    __syncthreads();

    float* sChunk = sm;
    float* sU  = sm + 4096;
    float* sG  = sm + 4096 + 32 * HS_STRIDE;
    float* sHo = sG + 32 * G_STRIDE;

#pragma unroll
    for (int k = 0; k < 8; k++) sU[tt * HS_STRIDE + e0 + k] = u[k];

    for (int jc = 0; jc < 4; jc++) {
        __syncthreads();
#pragma unroll
        for (int i = 0; i < 16; i++) {
            int idx = tid + i * 256;
            int d = idx >> 6, jj = idx & 63;
            sChunk[idx] = W1[d * 256 + jc * 64 + jj];
        }
        __syncthreads();
#pragma unroll
        for (int kk = 0; kk < 8; kk++) {
            int jl = eg + 8 * kk;
            int j  = jc * 64 + jl;
            float m = b1[j];
#pragma unroll 8
            for (int d = 0; d < 64; d++)
                m = fmaf(sU[tt * HS_STRIDE + d], sChunk[d * 64 + jl], m);
            float g = 0.5f * m * (1.f + erff(m * 0.70710678118654752f));
            sG[tt * G_STRIDE + j] = g;
        }
    }

    float o2[8];
#pragma unroll
    for (int k = 0; k < 8; k++) o2[k] = b2[e0 + k];
    for (int jc = 0; jc < 4; jc++) {
        __syncthreads();
#pragma unroll
        for (int i = 0; i < 16; i++) {
            int idx = tid + i * 256;
            int jj = idx >> 6, e = idx & 63;
            sChunk[idx] = W2[(jc * 64 + jj) * 64 + e];
        }
        __syncthreads();
#pragma unroll 8
        for (int jj = 0; jj < 64; jj++) {
            float gv = sG[tt * G_STRIDE + jc * 64 + jj];
            float4 w0 = *(const float4*)&sChunk[jj * 64 + e0];
            float4 w1 = *(const float4*)&sChunk[jj * 64 + e0 + 4];
            o2[0] = fmaf(gv, w0.x, o2[0]); o2[1] = fmaf(gv, w0.y, o2[1]);
            o2[2] = fmaf(gv, w0.z, o2[2]); o2[3] = fmaf(gv, w0.w, o2[3]);
            o2[4] = fmaf(gv, w1.x, o2[4]); o2[5] = fmaf(gv, w1.y, o2[5]);
            o2[6] = fmaf(gv, w1.z, o2[6]); o2[7] = fmaf(gv, w1.w, o2[7]);
        }
    }

#pragma unroll
    for (int k = 0; k < 8; k++)
        sHo[tt * HS_STRIDE + e0 + k] = u[k] + o2[k];

    float fo[8];
#pragma unroll
    for (int k = 0; k < 8; k++) fo[k] = bp[e0 + k];
    for (int dc = 0; dc < 2; dc++) {
        __syncthreads();
#pragma unroll
        for (int i = 0; i < 8; i++) {
            int idx = tid + i * 256;
            int d = idx >> 6, e = idx & 63;
            sChunk[idx] = Wp[(dc * 32 + d) * 64 + e];
        }
        __syncthreads();
#pragma unroll 8
        for (int d = 0; d < 32; d++) {
            float hv = sHo[tt * HS_STRIDE + dc * 32 + d];
            float4 w0 = *(const float4*)&sChunk[d * 64 + e0];
            float4 w1 = *(const float4*)&sChunk[d * 64 + e0 + 4];
            fo[0] = fmaf(hv, w0.x, fo[0]); fo[1] = fmaf(hv, w0.y, fo[1]);
            fo[2] = fmaf(hv, w0.z, fo[2]); fo[3] = fmaf(hv, w0.w, fo[3]);
            fo[4] = fmaf(hv, w1.x, fo[4]); fo[5] = fmaf(hv, w1.y, fo[5]);
            fo[6] = fmaf(hv, w1.z, fo[6]); fo[7] = fmaf(hv, w1.w, fo[7]);
        }
    }
#pragma unroll
    for (int k = 0; k < 8; k++)
        out[tok * DH + e0 + k] = fo[k];
}

// ---------------- launch ----------------
extern "C" void kernel_launch(void* const* d_in, const int* in_sizes, int n_in,
                              void* d_out, int out_size)
{
    const float* emb    = (const float*)d_in[0];
    const float* Wa     = (const float*)d_in[1];
    const float* ba     = (const float*)d_in[2];
    const float* Wb     = (const float*)d_in[3];
    const float* bb     = (const float*)d_in[4];
    const float* Wc     = (const float*)d_in[5];
    const float* bc     = (const float*)d_in[6];
    const float* head_w = (const float*)d_in[7];
    const float* hn_g   = (const float*)d_in[8];
    const float* hn_b   = (const float*)d_in[9];
    const float* Wd     = (const float*)d_in[10];
    const float* bd     = (const float*)d_in[11];
    const float* W1     = (const float*)d_in[12];
    const float* b1     = (const float*)d_in[13];
    const float* W2     = (const float*)d_in[14];
    const float* b2     = (const float*)d_in[15];
    const float* Wp     = (const float*)d_in[16];
    const float* bp     = (const float*)d_in[17];
    const float* ng     = (const float*)d_in[18];
    const float* nb     = (const float*)d_in[19];
    float* out = (float*)d_out;

    cudaFuncSetAttribute(gemm_tf32_kernel, cudaFuncAttributeMaxDynamicSharedMemorySize, GEMM_SMEM);
    cudaFuncSetAttribute(post_kernel, cudaFuncAttributeMaxDynamicSharedMemorySize, POST_BYTES);

    pack_w_kernel<<<(int)(((size_t)GNP * GK + 255) / 256), 256>>>(Wa, Wb, Wd);

    dim3 ggrid(GNP / 128, MT / 128);
    gemm_tf32_kernel<<<ggrid, 256, GEMM_SMEM>>>(emb, ba, bb, bd);

    scanA_kernel<<<128 * SCH, 64>>>();
    scanB_kernel<<<128, 64>>>();
    scanC_kernel<<<128 * SCH, 64>>>();

    post_kernel<<<MT / 32, 256, POST_BYTES>>>(Wc, bc, head_w, hn_g, hn_b,
                                              W1, b1, W2, b2, Wp, bp, ng, nb, out);
}

// round 7
// speedup vs baseline: 3.8615x; 1.1772x over previous
#include <cuda_runtime.h>
#include <cuda_bf16.h>
#include <math.h>
#include <stdint.h>

// Problem constants
#define EB 1024     // embed dim
#define DH 64       // head dim
#define NH 16       // heads
#define BB 8
#define LL 4096
#define MT (BB*LL)          // 32768 tokens
#define GN (2*EB + DH)      // 2112 real columns  [a | b | dx]
#define GNP 2176            // padded to 17 tiles of 128
#define GK EB

// ---------------- scratch ----------------
__device__ float g_a [ (size_t)MT * EB ];   // [B,L,H,D] tanh gate
__device__ float g_b [ (size_t)MT * EB ];   // [B,L,H,D] additive gate
__device__ float g_hs[ (size_t)MT * EB ];   // [B,L,H,D] scan output
__device__ float g_dx[ (size_t)MT * DH ];   // [B,L,D]
__device__ float g_wt[ (size_t)GNP * GK ];  // packed weights [n][k], tf32-rounded

// chunked-scan intermediates: [BH=128][CH=32][D=64]
#define SCH 32
#define SCL (LL / SCH)      // 128
__device__ float g_cp[128 * SCH * 64];
__device__ float g_cq[128 * SCH * 64];
__device__ float g_h0[128 * SCH * 64];

// ---------------- helpers ----------------
__device__ __forceinline__ uint32_t smem_u32(const void* p) {
    uint32_t r;
    asm("{ .reg .u64 t; cvta.to.shared.u64 t, %1; cvt.u32.u64 %0, t; }" : "=r"(r) : "l"(p));
    return r;
}
__device__ __forceinline__ void cp_async16(uint32_t dst, const void* src) {
    asm volatile("cp.async.cg.shared.global [%0], [%1], 16;" :: "r"(dst), "l"(src) : "memory");
}
__device__ __forceinline__ void cp_commit() {
    asm volatile("cp.async.commit_group;" ::: "memory");
}
__device__ __forceinline__ uint32_t tf32u(float x) {
    uint32_t u;
    asm("cvt.rna.tf32.f32 %0, %1;" : "=r"(u) : "f"(x));
    return u;
}
__device__ __forceinline__ void mma_tf32(float* c,
                                         uint32_t a0, uint32_t a1, uint32_t a2, uint32_t a3,
                                         uint32_t b0, uint32_t b1) {
    asm volatile(
        "mma.sync.aligned.m16n8k8.row.col.f32.tf32.tf32.f32 "
        "{%0,%1,%2,%3}, {%4,%5,%6,%7}, {%8,%9}, {%0,%1,%2,%3};"
        : "+f"(c[0]), "+f"(c[1]), "+f"(c[2]), "+f"(c[3])
        : "r"(a0), "r"(a1), "r"(a2), "r"(a3), "r"(b0), "r"(b1));
}

// ---------------- kernel: pack weights [n][k] K-major, tf32-rounded ----------------
__global__ void pack_w_kernel(const float* __restrict__ Wa,
                              const float* __restrict__ Wb,
                              const float* __restrict__ Wd)
{
    size_t idx = (size_t)blockIdx.x * 256 + threadIdx.x;
    if (idx >= (size_t)GNP * GK) return;
    int n = (int)(idx >> 10);
    int k = (int)(idx & 1023);
    float v = 0.f;
    if (n < 1024) {
        v = Wa[(size_t)(n >> 6) * (EB * DH) + (size_t)k * DH + (n & 63)];
    } else if (n < 2048) {
        int n2 = n - 1024;
        v = Wb[(size_t)(n2 >> 6) * (EB * DH) + (size_t)k * DH + (n2 & 63)];
    } else if (n < 2112) {
        v = Wd[(size_t)k * DH + (n - 2048)];
    }
    g_wt[idx] = __uint_as_float(tf32u(v));
}

// ---------------- kernel: TF32 gates GEMM (3-stage pipeline) ----------------
#define KC 32
#define NKC (GK / KC)          // 32
#define ROWB 128
#define TILEB (128 * ROWB)     // 16384
#define STAGEB (2 * TILEB)     // A + B = 32768
#define GEMM_SMEM (3 * STAGEB) // 98304 (>= epilogue sD 67584)

#define SWZ(row, chunk) ((uint32_t)((row) * ROWB + ((((chunk) ^ (((row) & 1) << 2))) << 4)))

__device__ __forceinline__ void gemm_load_stage(uint32_t sst, int kc, int tid,
                                                const char* Ag, const char* Bg)
{
    const size_t kb = (size_t)kc * 128;   // byte offset in K
#pragma unroll
    for (int j = 0; j < 4; j++) {
        int id  = tid + j * 256;
        int row = id >> 3;
        int c   = id & 7;
        cp_async16(sst + SWZ(row, c),         Ag + (size_t)row * 4096 + kb + c * 16);
        cp_async16(sst + TILEB + SWZ(row, c), Bg + (size_t)row * 4096 + kb + c * 16);
    }
}

__global__ void __launch_bounds__(256)
gemm_tf32_kernel(const float* __restrict__ emb,
                 const float* __restrict__ ba,
                 const float* __restrict__ bb,
                 const float* __restrict__ bd)
{
    extern __shared__ char sm_raw[];
    const int tid  = threadIdx.x;
    const int wid  = tid >> 5;
    const int lane = tid & 31;
    const uint32_t sbase = smem_u32(sm_raw);

    const long m0 = (long)blockIdx.y * 128;
    const int  n0 = blockIdx.x * 128;
    const int  wm = (wid & 3) * 32;
    const int  wn = (wid >> 2) * 64;

    const char* Ag = (const char*)(emb  + (size_t)m0 * GK);
    const char* Bg = (const char*)(g_wt + (size_t)n0 * GK);

    float acc[2][8][4];
#pragma unroll
    for (int i = 0; i < 2; i++)
#pragma unroll
        for (int j = 0; j < 8; j++)
#pragma unroll
            for (int q = 0; q < 4; q++) acc[i][j][q] = 0.f;

    // prologue: stages 0, 1
    gemm_load_stage(sbase, 0, tid, Ag, Bg);
    cp_commit();
    gemm_load_stage(sbase + STAGEB, 1, tid, Ag, Bg);
    cp_commit();

    const int lrow4 = lane >> 2;         // 0..7
    const int lch   = lane & 3;          // chunk within k16 half

    int stage = 0;
    for (int kc = 0; kc < NKC; kc++) {
        if (kc + 1 < NKC) {
            asm volatile("cp.async.wait_group 1;" ::: "memory");
        } else {
            asm volatile("cp.async.wait_group 0;" ::: "memory");
        }
        __syncthreads();
        if (kc + 2 < NKC) {
            int nstage = stage + 2; if (nstage >= 3) nstage -= 3;
            gemm_load_stage(sbase + nstage * STAGEB, kc + 2, tid, Ag, Bg);
            cp_commit();
        }

        const char* sA = sm_raw + stage * STAGEB;
        const char* sB = sA + TILEB;

#pragma unroll
        for (int k16 = 0; k16 < 2; k16++) {
            const int ch = k16 * 4 + lch;
            uint32_t aw[2][2][4];
#pragma unroll
            for (int mt = 0; mt < 2; mt++) {
#pragma unroll
                for (int hh = 0; hh < 2; hh++) {
                    int row = wm + mt * 16 + hh * 8 + lrow4;
                    float4 v = *(const float4*)(sA + SWZ(row, ch));
                    aw[mt][hh][0] = tf32u(v.x);
                    aw[mt][hh][1] = tf32u(v.y);
                    aw[mt][hh][2] = tf32u(v.z);
                    aw[mt][hh][3] = tf32u(v.w);
                }
            }
#pragma unroll
            for (int g = 0; g < 8; g++) {
                int row = wn + g * 8 + lrow4;
                float4 bv = *(const float4*)(sB + SWZ(row, ch));
                uint32_t b0 = __float_as_uint(bv.x);
                uint32_t b1 = __float_as_uint(bv.y);
                uint32_t b2 = __float_as_uint(bv.z);
                uint32_t b3 = __float_as_uint(bv.w);
                mma_tf32(acc[0][g], aw[0][0][0], aw[0][1][0], aw[0][0][1], aw[0][1][1], b0, b1);
                mma_tf32(acc[0][g], aw[0][0][2], aw[0][1][2], aw[0][0][3], aw[0][1][3], b2, b3);
                mma_tf32(acc[1][g], aw[1][0][0], aw[1][1][0], aw[1][0][1], aw[1][1][1], b0, b1);
                mma_tf32(acc[1][g], aw[1][0][2], aw[1][1][2], aw[1][0][3], aw[1][1][3], b2, b3);
            }
        }
        stage++; if (stage == 3) stage = 0;
    }
    __syncthreads();

    // ---- epilogue ----
    float* sD = (float*)sm_raw;   // 128 x 132
#pragma unroll
    for (int mt = 0; mt < 2; mt++) {
#pragma unroll
        for (int g = 0; g < 8; g++) {
            int ml = wm + mt * 16 + (lane >> 2);
            int nl = wn + g * 8 + (lane & 3) * 2;
            *(float2*)&sD[ml * 132 + nl]       = make_float2(acc[mt][g][0], acc[mt][g][1]);
            *(float2*)&sD[(ml + 8) * 132 + nl] = make_float2(acc[mt][g][2], acc[mt][g][3]);
        }
    }
    __syncthreads();

    for (int i = tid; i < 128 * 128; i += 256) {
        int mm = i >> 7;
        int nn = i & 127;
        int ng = n0 + nn;
        float c = sD[mm * 132 + nn];
        long m = m0 + mm;
        if (ng < 1024) {
            g_a[m * EB + ng] = tanhf(c + ba[ng]);
        } else if (ng < 2048) {
            g_b[m * EB + (ng - 1024)] = c + bb[ng - 1024];
        } else if (ng < 2112) {
            g_dx[m * DH + (ng - 2048)] = c + bd[ng - 2048];
        }
    }
}

// ---------------- chunked scan, wide-coalesced ----------------
// Block per (b, chunk): 1024 threads cover full EB row -> 4KB contiguous loads.
__global__ void __launch_bounds__(1024)
scanA_kernel()
{
    const int b = blockIdx.x >> 5;
    const int c = blockIdx.x & 31;
    const int e = threadIdx.x;            // 0..1023 = h*64+d
    size_t base = ((size_t)b * LL + (size_t)c * SCL) * EB + e;
    float P = 1.f, Q = 0.f;
#pragma unroll 8
    for (int l = 0; l < SCL; l++) {
        size_t idx = base + (size_t)l * EB;
        float av = g_a[idx];
        float bv = g_b[idx];
        Q = fmaf(av, Q, bv);
        P *= av;
    }
    int bh = b * 16 + (e >> 6);
    g_cp[(bh * SCH + c) * 64 + (e & 63)] = P;
    g_cq[(bh * SCH + c) * 64 + (e & 63)] = Q;
}

__global__ void __launch_bounds__(64)
scanB_kernel()
{
    const int bh = blockIdx.x;
    const int d  = threadIdx.x;
    float hv = 0.f;
#pragma unroll
    for (int c = 0; c < SCH; c++) {
        int i = (bh * SCH + c) * 64 + d;
        g_h0[i] = hv;
        hv = fmaf(g_cp[i], hv, g_cq[i]);
    }
}

__global__ void __launch_bounds__(1024)
scanC_kernel()
{
    const int b = blockIdx.x >> 5;
    const int c = blockIdx.x & 31;
    const int e = threadIdx.x;
    int bh = b * 16 + (e >> 6);
    float hv = g_h0[(bh * SCH + c) * 64 + (e & 63)];
    size_t base = ((size_t)b * LL + (size_t)c * SCL) * EB + e;
#pragma unroll 8
    for (int l = 0; l < SCL; l++) {
        size_t idx = base + (size_t)l * EB;
        float av = g_a[idx];
        float bv = g_b[idx];
        hv = fmaf(av, hv, bv);
        g_hs[idx] = hv;
    }
}

// ---------------- kernel 3: fused per-token epilogue ----------------
// 64 tokens/block (2 per thread -> weight fragments reused), 256 threads.
// Phase A: [Wc0|Wc1|hs0|hs1] = 16896 floats. Phase B: 21248 floats = 85KB.
#define TOK 64
#define HS_STRIDE 68
#define POST_FLOATS 21248
#define POST_BYTES  (POST_FLOATS * 4)

__device__ __forceinline__ float grp8_sum(float v) {
    v += __shfl_xor_sync(0xffffffffu, v, 1);
    v += __shfl_xor_sync(0xffffffffu, v, 2);
    v += __shfl_xor_sync(0xffffffffu, v, 4);
    return v;
}

__device__ __forceinline__ void post_prefetch(uint32_t swc, uint32_t shs,
                                              const float* __restrict__ Wc,
                                              int h, long token0, int tid)
{
    const char* wsrc = (const char*)(Wc + (size_t)h * 4096);
#pragma unroll
    for (int i = 0; i < 4; i++) {
        int idx = tid + i * 256;                 // 0..1023 16B chunks
        cp_async16(swc + idx * 16, wsrc + idx * 16);
    }
#pragma unroll
    for (int i = 0; i < 4; i++) {
        int idx = tid + i * 256;                 // 0..1023
        int t = idx >> 4;                        // token 0..63
        int c = idx & 15;
        const char* hsrc = (const char*)(g_hs + (token0 + t) * (size_t)EB + h * 64);
        cp_async16(shs + (uint32_t)(t * HS_STRIDE * 4 + c * 16), hsrc + c * 16);
    }
}

__global__ void __launch_bounds__(256)
post_kernel(const float* __restrict__ Wc,  const float* __restrict__ bc,
            const float* __restrict__ head_w,
            const float* __restrict__ hn_g, const float* __restrict__ hn_b,
            const float* __restrict__ W1,  const float* __restrict__ b1,
            const float* __restrict__ W2,  const float* __restrict__ b2,
            const float* __restrict__ Wp,  const float* __restrict__ bp,
            const float* __restrict__ ng,  const float* __restrict__ nb,
            float* __restrict__ out)
{
    extern __shared__ float sm[];
    const int tid = threadIdx.x;
    const int tt  = tid >> 3;     // 0..31, tokens tt and tt+32
    const int eg  = tid & 7;
    const int e0  = eg * 8;
    const long token0 = (long)blockIdx.x * TOK;
    const long tok0 = token0 + tt;
    const long tok1 = token0 + tt + 32;

    const uint32_t swc_u0 = smem_u32(sm);
    const uint32_t swc_u1 = smem_u32(sm + 4096);
    const uint32_t shs_u0 = smem_u32(sm + 8192);
    const uint32_t shs_u1 = smem_u32(sm + 8192 + TOK * HS_STRIDE);

    float dxv0[8], dxv1[8], acc0[8], acc1[8];
#pragma unroll
    for (int k = 0; k < 8; k++) {
        dxv0[k] = g_dx[tok0 * DH + e0 + k];
        dxv1[k] = g_dx[tok1 * DH + e0 + k];
        acc0[k] = dxv0[k];
        acc1[k] = dxv1[k];
    }

    post_prefetch(swc_u0, shs_u0, Wc, 0, token0, tid);
    cp_commit();

    for (int h = 0; h < NH; h++) {
        const int cur = h & 1;
        if (h + 1 < NH) {
            post_prefetch(cur ? swc_u0 : swc_u1, cur ? shs_u0 : shs_u1, Wc, h + 1, token0, tid);
            cp_commit();
            asm volatile("cp.async.wait_group 1;" ::: "memory");
        } else {
            asm volatile("cp.async.wait_group 0;" ::: "memory");
        }
        __syncthreads();

        const float* sWc = sm + (cur ? 4096 : 0);
        const float* sHs = sm + 8192 + (cur ? TOK * HS_STRIDE : 0);

        float o0[8], o1[8];
#pragma unroll
        for (int k = 0; k < 8; k++) {
            float bck = bc[h * DH + e0 + k];
            o0[k] = bck + dxv0[k];
            o1[k] = bck + dxv1[k];
        }
#pragma unroll 8
        for (int d = 0; d < 64; d++) {
            float hv0 = sHs[tt * HS_STRIDE + d];
            float hv1 = sHs[(tt + 32) * HS_STRIDE + d];
            float4 w0 = *(const float4*)&sWc[d * 64 + e0];
            float4 w1 = *(const float4*)&sWc[d * 64 + e0 + 4];
            o0[0] = fmaf(hv0, w0.x, o0[0]); o0[1] = fmaf(hv0, w0.y, o0[1]);
            o0[2] = fmaf(hv0, w0.z, o0[2]); o0[3] = fmaf(hv0, w0.w, o0[3]);
            o0[4] = fmaf(hv0, w1.x, o0[4]); o0[5] = fmaf(hv0, w1.y, o0[5]);
            o0[6] = fmaf(hv0, w1.z, o0[6]); o0[7] = fmaf(hv0, w1.w, o0[7]);
            o1[0] = fmaf(hv1, w0.x, o1[0]); o1[1] = fmaf(hv1, w0.y, o1[1]);
            o1[2] = fmaf(hv1, w0.z, o1[2]); o1[3] = fmaf(hv1, w0.w, o1[3]);
            o1[4] = fmaf(hv1, w1.x, o1[4]); o1[5] = fmaf(hv1, w1.y, o1[5]);
            o1[6] = fmaf(hv1, w1.z, o1[6]); o1[7] = fmaf(hv1, w1.w, o1[7]);
        }
        float s10 = 0.f, s20 = 0.f, s11 = 0.f, s21 = 0.f;
#pragma unroll
        for (int k = 0; k < 8; k++) {
            s10 += o0[k]; s20 += o0[k] * o0[k];
            s11 += o1[k]; s21 += o1[k] * o1[k];
        }
        s10 = grp8_sum(s10); s20 = grp8_sum(s20);
        s11 = grp8_sum(s11); s21 = grp8_sum(s21);
        float mean0 = s10 * (1.f / 64.f);
        float var0  = s20 * (1.f / 64.f) - mean0 * mean0;
        float rstd0 = rsqrtf(var0 + 1e-5f);
        float mean1 = s11 * (1.f / 64.f);
        float var1  = s21 * (1.f / 64.f) - mean1 * mean1;
        float rstd1 = rsqrtf(var1 + 1e-5f);
        float hw = head_w[h];
#pragma unroll
        for (int k = 0; k < 8; k++) {
            float gk = hn_g[h * DH + e0 + k];
            float bk = hn_b[h * DH + e0 + k];
            acc0[k] = fmaf(hw, (o0[k] - mean0) * rstd0 * gk + bk, acc0[k]);
            acc1[k] = fmaf(hw, (o1[k] - mean1) * rstd1 * gk + bk, acc1[k]);
        }
        __syncthreads();
    }

    float u0[8], u1[8];
    {
        float s10 = 0.f, s20 = 0.f, s11 = 0.f, s21 = 0.f;
#pragma unroll
        for (int k = 0; k < 8; k++) {
            acc0[k] *= (1.f / (float)NH);
            acc1[k] *= (1.f / (float)NH);
            s10 += acc0[k]; s20 += acc0[k] * acc0[k];
            s11 += acc1[k]; s21 += acc1[k] * acc1[k];
        }
        s10 = grp8_sum(s10); s20 = grp8_sum(s20);
        s11 = grp8_sum(s11); s21 = grp8_sum(s21);
        float mean0 = s10 * (1.f / 64.f);
        float var0  = s20 * (1.f / 64.f) - mean0 * mean0;
        float rstd0 = rsqrtf(var0 + 1e-5f);
        float mean1 = s11 * (1.f / 64.f);
        float var1  = s21 * (1.f / 64.f) - mean1 * mean1;
        float rstd1 = rsqrtf(var1 + 1e-5f);
#pragma unroll
        for (int k = 0; k < 8; k++) {
            float ngk = ng[e0 + k], nbk = nb[e0 + k];
            u0[k] = acc0[k] + (acc0[k] - mean0) * rstd0 * ngk + nbk;
            u1[k] = acc1[k] + (acc1[k] - mean1) * rstd1 * ngk + nbk;
        }
    }

    // ---- Phase B ----
    float* sW1c = sm;                       // 4096
    float* sW2c = sm + 4096;                // 4096
    float* sU   = sm + 8192;                // 64*68
    float* sGc  = sm + 8192 + TOK * HS_STRIDE;   // 64*68
    float* sHo  = sm + 8192 + 2 * TOK * HS_STRIDE; // 64*68

#pragma unroll
    for (int k = 0; k < 8; k++) {
        sU[tt * HS_STRIDE + e0 + k]        = u0[k];
        sU[(tt + 32) * HS_STRIDE + e0 + k] = u1[k];
    }

    float o20[8], o21[8];
#pragma unroll
    for (int k = 0; k < 8; k++) { o20[k] = b2[e0 + k]; o21[k] = o20[k]; }

    for (int jc = 0; jc < 4; jc++) {
        __syncthreads();
#pragma unroll
        for (int i = 0; i < 16; i++) {
            int idx = tid + i * 256;            // 0..4095
            int d = idx >> 6, jj = idx & 63;
            sW1c[idx] = W1[d * 256 + jc * 64 + jj];
            sW2c[idx] = W2[(jc * 64 + (idx >> 6)) * 64 + (idx & 63)];
        }
        __syncthreads();
        // mid + gelu for this chunk (local jl 0..63)
#pragma unroll
        for (int kk = 0; kk < 8; kk++) {
            int jl = eg + 8 * kk;
            float m0 = b1[jc * 64 + jl], m1 = m0;
#pragma unroll 8
            for (int d = 0; d < 64; d++) {
                float w = sW1c[d * 64 + jl];
                m0 = fmaf(sU[tt * HS_STRIDE + d], w, m0);
                m1 = fmaf(sU[(tt + 32) * HS_STRIDE + d], w, m1);
            }
            sGc[tt * HS_STRIDE + jl]        = 0.5f * m0 * (1.f + erff(m0 * 0.70710678118654752f));
            sGc[(tt + 32) * HS_STRIDE + jl] = 0.5f * m1 * (1.f + erff(m1 * 0.70710678118654752f));
        }
        __syncthreads();
        // accumulate W2 chunk
#pragma unroll 8
        for (int jj = 0; jj < 64; jj++) {
            float gv0 = sGc[tt * HS_STRIDE + jj];
            float gv1 = sGc[(tt + 32) * HS_STRIDE + jj];
            float4 w0 = *(const float4*)&sW2c[jj * 64 + e0];
            float4 w1 = *(const float4*)&sW2c[jj * 64 + e0 + 4];
            o20[0] = fmaf(gv0, w0.x, o20[0]); o20[1] = fmaf(gv0, w0.y, o20[1]);
            o20[2] = fmaf(gv0, w0.z, o20[2]); o20[3] = fmaf(gv0, w0.w, o20[3]);
            o20[4] = fmaf(gv0, w1.x, o20[4]); o20[5] = fmaf(gv0, w1.y, o20[5]);
            o20[6] = fmaf(gv0, w1.z, o20[6]); o20[7] = fmaf(gv0, w1.w, o20[7]);
            o21[0] = fmaf(gv1, w0.x, o21[0]); o21[1] = fmaf(gv1, w0.y, o21[1]);
            o21[2] = fmaf(gv1, w0.z, o21[2]); o21[3] = fmaf(gv1, w0.w, o21[3]);
            o21[4] = fmaf(gv1, w1.x, o21[4]); o21[5] = fmaf(gv1, w1.y, o21[5]);
            o21[6] = fmaf(gv1, w1.z, o21[6]); o21[7] = fmaf(gv1, w1.w, o21[7]);
        }
    }

    __syncthreads();
#pragma unroll
    for (int k = 0; k < 8; k++) {
        sHo[tt * HS_STRIDE + e0 + k]        = u0[k] + o20[k];
        sHo[(tt + 32) * HS_STRIDE + e0 + k] = u1[k] + o21[k];
    }

    float fo0[8], fo1[8];
#pragma unroll
    for (int k = 0; k < 8; k++) { fo0[k] = bp[e0 + k]; fo1[k] = fo0[k]; }
    for (int dc = 0; dc < 2; dc++) {
        __syncthreads();
#pragma unroll
        for (int i = 0; i < 8; i++) {
            int idx = tid + i * 256;            // 0..2047 = d*64+e
            int d = idx >> 6, e = idx & 63;
            sW1c[idx] = Wp[(dc * 32 + d) * 64 + e];
        }
        __syncthreads();
#pragma unroll 8
        for (int d = 0; d < 32; d++) {
            float hv0 = sHo[tt * HS_STRIDE + dc * 32 + d];
            float hv1 = sHo[(tt + 32) * HS_STRIDE + dc * 32 + d];
            float4 w0 = *(const float4*)&sW1c[d * 64 + e0];
            float4 w1 = *(const float4*)&sW1c[d * 64 + e0 + 4];
            fo0[0] = fmaf(hv0, w0.x, fo0[0]); fo0[1] = fmaf(hv0, w0.y, fo0[1]);
            fo0[2] = fmaf(hv0, w0.z, fo0[2]); fo0[3] = fmaf(hv0, w0.w, fo0[3]);
            fo0[4] = fmaf(hv0, w1.x, fo0[4]); fo0[5] = fmaf(hv0, w1.y, fo0[5]);
            fo0[6] = fmaf(hv0, w1.z, fo0[6]); fo0[7] = fmaf(hv0, w1.w, fo0[7]);
            fo1[0] = fmaf(hv1, w0.x, fo1[0]); fo1[1] = fmaf(hv1, w0.y, fo1[1]);
            fo1[2] = fmaf(hv1, w0.z, fo1[2]); fo1[3] = fmaf(hv1, w0.w, fo1[3]);
            fo1[4] = fmaf(hv1, w1.x, fo1[4]); fo1[5] = fmaf(hv1, w1.y, fo1[5]);
            fo1[6] = fmaf(hv1, w1.z, fo1[6]); fo1[7] = fmaf(hv1, w1.w, fo1[7]);
        }
    }
#pragma unroll
    for (int k = 0; k < 8; k++) {
        out[tok0 * DH + e0 + k] = fo0[k];
        out[tok1 * DH + e0 + k] = fo1[k];
    }
}

// ---------------- launch ----------------
extern "C" void kernel_launch(void* const* d_in, const int* in_sizes, int n_in,
                              void* d_out, int out_size)
{
    const float* emb    = (const float*)d_in[0];
    const float* Wa     = (const float*)d_in[1];
    const float* ba     = (const float*)d_in[2];
    const float* Wb     = (const float*)d_in[3];
    const float* bb     = (const float*)d_in[4];
    const float* Wc     = (const float*)d_in[5];
    const float* bc     = (const float*)d_in[6];
    const float* head_w = (const float*)d_in[7];
    const float* hn_g   = (const float*)d_in[8];
    const float* hn_b   = (const float*)d_in[9];
    const float* Wd     = (const float*)d_in[10];
    const float* bd     = (const float*)d_in[11];
    const float* W1     = (const float*)d_in[12];
    const float* b1     = (const float*)d_in[13];
    const float* W2     = (const float*)d_in[14];
    const float* b2     = (const float*)d_in[15];
    const float* Wp     = (const float*)d_in[16];
    const float* bp     = (const float*)d_in[17];
    const float* ng     = (const float*)d_in[18];
    const float* nb     = (const float*)d_in[19];
    float* out = (float*)d_out;

    cudaFuncSetAttribute(gemm_tf32_kernel, cudaFuncAttributeMaxDynamicSharedMemorySize, GEMM_SMEM);
    cudaFuncSetAttribute(post_kernel, cudaFuncAttributeMaxDynamicSharedMemorySize, POST_BYTES);

    pack_w_kernel<<<(int)(((size_t)GNP * GK + 255) / 256), 256>>>(Wa, Wb, Wd);

    dim3 ggrid(GNP / 128, MT / 128);
    gemm_tf32_kernel<<<ggrid, 256, GEMM_SMEM>>>(emb, ba, bb, bd);

    scanA_kernel<<<BB * SCH, 1024>>>();
    scanB_kernel<<<128, 64>>>();
    scanC_kernel<<<BB * SCH, 1024>>>();

    post_kernel<<<MT / TOK, 256, POST_BYTES>>>(Wc, bc, head_w, hn_g, hn_b,
                                               W1, b1, W2, b2, Wp, bp, ng, nb, out);
}

// round 8
// speedup vs baseline: 3.8828x; 1.0055x over previous
#include <cuda_runtime.h>
#include <cuda_bf16.h>
#include <math.h>
#include <stdint.h>

// Problem constants
#define EB 1024     // embed dim
#define DH 64       // head dim
#define NH 16       // heads
#define BB 8
#define LL 4096
#define MT (BB*LL)          // 32768 tokens
#define GN (2*EB + DH)      // 2112 real columns  [a | b | dx]
#define GNP 2176            // padded to 17 tiles of 128
#define GK EB

// ---------------- scratch ----------------
__device__ float g_a [ (size_t)MT * EB ];   // [B,L,H,D] tanh gate
__device__ float g_b [ (size_t)MT * EB ];   // [B,L,H,D] additive gate
__device__ float g_hs[ (size_t)MT * EB ];   // [B,L,H,D] scan output
__device__ float g_dx[ (size_t)MT * DH ];   // [B,L,D]
__device__ float g_wt[ (size_t)GNP * GK ];  // packed weights [n][k], tf32-rounded

// chunked-scan intermediates: [BH=128][CH=32][D=64]
#define SCH 32
#define SCL (LL / SCH)      // 128
__device__ float g_cp[128 * SCH * 64];
__device__ float g_cq[128 * SCH * 64];

// ---------------- helpers ----------------
__device__ __forceinline__ uint32_t smem_u32(const void* p) {
    uint32_t r;
    asm("{ .reg .u64 t; cvta.to.shared.u64 t, %1; cvt.u32.u64 %0, t; }" : "=r"(r) : "l"(p));
    return r;
}
__device__ __forceinline__ void cp_async16(uint32_t dst, const void* src) {
    asm volatile("cp.async.cg.shared.global [%0], [%1], 16;" :: "r"(dst), "l"(src) : "memory");
}
__device__ __forceinline__ void cp_commit() {
    asm volatile("cp.async.commit_group;" ::: "memory");
}
__device__ __forceinline__ uint32_t tf32u(float x) {
    uint32_t u;
    asm("cvt.rna.tf32.f32 %0, %1;" : "=r"(u) : "f"(x));
    return u;
}
__device__ __forceinline__ void mma_tf32(float* c,
                                         uint32_t a0, uint32_t a1, uint32_t a2, uint32_t a3,
                                         uint32_t b0, uint32_t b1) {
    asm volatile(
        "mma.sync.aligned.m16n8k8.row.col.f32.tf32.tf32.f32 "
        "{%0,%1,%2,%3}, {%4,%5,%6,%7}, {%8,%9}, {%0,%1,%2,%3};"
        : "+f"(c[0]), "+f"(c[1]), "+f"(c[2]), "+f"(c[3])
        : "r"(a0), "r"(a1), "r"(a2), "r"(a3), "r"(b0), "r"(b1));
}
// fast accurate tanh: clamp + expf identity (err ~1e-6)
__device__ __forceinline__ float tanh_fast(float x) {
    float xc = fminf(fmaxf(x, -10.f), 10.f);
    float t  = __expf(2.f * xc);
    return __fdividef(t - 1.f, t + 1.f);
}

// ---------------- pack kernels (split to steer ncu capture onto gemm) ----------------
// g_wt layout [n][k], n: [0,1024)=Wa, [1024,2048)=Wb, [2048,2176)=Wd|zero
__global__ void pack_ab_kernel(const float* __restrict__ W, int n_off)
{
    size_t idx = (size_t)blockIdx.x * 256 + threadIdx.x;   // < 1024*1024
    int n_local = (int)(idx >> 10);
    int k = (int)(idx & 1023);
    float v = W[(size_t)(n_local >> 6) * (EB * DH) + (size_t)k * DH + (n_local & 63)];
    g_wt[(size_t)(n_off + n_local) * 1024 + k] = __uint_as_float(tf32u(v));
}
__global__ void pack_d_kernel(const float* __restrict__ Wd)
{
    size_t idx = (size_t)blockIdx.x * 256 + threadIdx.x;   // < 128*1024
    int n_local = (int)(idx >> 10);
    int k = (int)(idx & 1023);
    float v = (n_local < 64) ? Wd[(size_t)k * DH + n_local] : 0.f;
    g_wt[(size_t)(2048 + n_local) * 1024 + k] = __uint_as_float(tf32u(v));
}

// ---------------- kernel: TF32 gates GEMM (3-stage pipeline) ----------------
#define KC 32
#define NKC (GK / KC)          // 32
#define ROWB 128
#define TILEB (128 * ROWB)     // 16384
#define STAGEB (2 * TILEB)     // A + B = 32768
#define GEMM_SMEM (3 * STAGEB) // 98304 (>= epilogue sD 67584)

#define SWZ(row, chunk) ((uint32_t)((row) * ROWB + ((((chunk) ^ (((row) & 1) << 2))) << 4)))

__device__ __forceinline__ void gemm_load_stage(uint32_t sst, int kc, int tid,
                                                const char* Ag, const char* Bg)
{
    const size_t kb = (size_t)kc * 128;   // byte offset in K
#pragma unroll
    for (int j = 0; j < 4; j++) {
        int id  = tid + j * 256;
        int row = id >> 3;
        int c   = id & 7;
        cp_async16(sst + SWZ(row, c),         Ag + (size_t)row * 4096 + kb + c * 16);
        cp_async16(sst + TILEB + SWZ(row, c), Bg + (size_t)row * 4096 + kb + c * 16);
    }
}

__global__ void __launch_bounds__(256)
gemm_tf32_kernel(const float* __restrict__ emb,
                 const float* __restrict__ ba,
                 const float* __restrict__ bb,
                 const float* __restrict__ bd)
{
    extern __shared__ char sm_raw[];
    const int tid  = threadIdx.x;
    const int wid  = tid >> 5;
    const int lane = tid & 31;
    const uint32_t sbase = smem_u32(sm_raw);

    const long m0 = (long)blockIdx.y * 128;
    const int  n0 = blockIdx.x * 128;
    const int  wm = (wid & 3) * 32;
    const int  wn = (wid >> 2) * 64;

    const char* Ag = (const char*)(emb  + (size_t)m0 * GK);
    const char* Bg = (const char*)(g_wt + (size_t)n0 * GK);

    float acc[2][8][4];
#pragma unroll
    for (int i = 0; i < 2; i++)
#pragma unroll
        for (int j = 0; j < 8; j++)
#pragma unroll
            for (int q = 0; q < 4; q++) acc[i][j][q] = 0.f;

    gemm_load_stage(sbase, 0, tid, Ag, Bg);
    cp_commit();
    gemm_load_stage(sbase + STAGEB, 1, tid, Ag, Bg);
    cp_commit();

    const int lrow4 = lane >> 2;         // 0..7
    const int lch   = lane & 3;          // chunk within k16 half

    int stage = 0;
    for (int kc = 0; kc < NKC; kc++) {
        if (kc + 1 < NKC) {
            asm volatile("cp.async.wait_group 1;" ::: "memory");
        } else {
            asm volatile("cp.async.wait_group 0;" ::: "memory");
        }
        __syncthreads();
        if (kc + 2 < NKC) {
            int nstage = stage + 2; if (nstage >= 3) nstage -= 3;
            gemm_load_stage(sbase + nstage * STAGEB, kc + 2, tid, Ag, Bg);
            cp_commit();
        }

        const char* sA = sm_raw + stage * STAGEB;
        const char* sB = sA + TILEB;

#pragma unroll
        for (int k16 = 0; k16 < 2; k16++) {
            const int ch = k16 * 4 + lch;
            uint32_t aw[2][2][4];
#pragma unroll
            for (int mt = 0; mt < 2; mt++) {
#pragma unroll
                for (int hh = 0; hh < 2; hh++) {
                    int row = wm + mt * 16 + hh * 8 + lrow4;
                    float4 v = *(const float4*)(sA + SWZ(row, ch));
                    aw[mt][hh][0] = tf32u(v.x);
                    aw[mt][hh][1] = tf32u(v.y);
                    aw[mt][hh][2] = tf32u(v.z);
                    aw[mt][hh][3] = tf32u(v.w);
                }
            }
#pragma unroll
            for (int g = 0; g < 8; g++) {
                int row = wn + g * 8 + lrow4;
                float4 bv = *(const float4*)(sB + SWZ(row, ch));
                uint32_t b0 = __float_as_uint(bv.x);
                uint32_t b1 = __float_as_uint(bv.y);
                uint32_t b2 = __float_as_uint(bv.z);
                uint32_t b3 = __float_as_uint(bv.w);
                mma_tf32(acc[0][g], aw[0][0][0], aw[0][1][0], aw[0][0][1], aw[0][1][1], b0, b1);
                mma_tf32(acc[0][g], aw[0][0][2], aw[0][1][2], aw[0][0][3], aw[0][1][3], b2, b3);
                mma_tf32(acc[1][g], aw[1][0][0], aw[1][1][0], aw[1][0][1], aw[1][1][1], b0, b1);
                mma_tf32(acc[1][g], aw[1][0][2], aw[1][1][2], aw[1][0][3], aw[1][1][3], b2, b3);
            }
        }
        stage++; if (stage == 3) stage = 0;
    }
    __syncthreads();

    // ---- epilogue ----
    float* sD = (float*)sm_raw;   // 128 x 132
#pragma unroll
    for (int mt = 0; mt < 2; mt++) {
#pragma unroll
        for (int g = 0; g < 8; g++) {
            int ml = wm + mt * 16 + (lane >> 2);
            int nl = wn + g * 8 + (lane & 3) * 2;
            *(float2*)&sD[ml * 132 + nl]       = make_float2(acc[mt][g][0], acc[mt][g][1]);
            *(float2*)&sD[(ml + 8) * 132 + nl] = make_float2(acc[mt][g][2], acc[mt][g][3]);
        }
    }
    __syncthreads();

    for (int i = tid; i < 128 * 128; i += 256) {
        int mm = i >> 7;
        int nn = i & 127;
        int ng = n0 + nn;
        float c = sD[mm * 132 + nn];
        long m = m0 + mm;
        if (ng < 1024) {
            g_a[m * EB + ng] = tanh_fast(c + ba[ng]);
        } else if (ng < 2048) {
            g_b[m * EB + (ng - 1024)] = c + bb[ng - 1024];
        } else if (ng < 2112) {
            g_dx[m * DH + (ng - 2048)] = c + bd[ng - 2048];
        }
    }
}

// ---------------- chunked scan (2 kernels; combine fused into scanC) ----------------
__global__ void __launch_bounds__(1024)
scanA_kernel()
{
    const int b = blockIdx.x >> 5;
    const int c = blockIdx.x & 31;
    const int e = threadIdx.x;            // 0..1023 = h*64+d
    size_t base = ((size_t)b * LL + (size_t)c * SCL) * EB + e;
    float P = 1.f, Q = 0.f;
#pragma unroll 8
    for (int l = 0; l < SCL; l++) {
        size_t idx = base + (size_t)l * EB;
        float av = g_a[idx];
        float bv = g_b[idx];
        Q = fmaf(av, Q, bv);
        P *= av;
    }
    int bh = b * 16 + (e >> 6);
    g_cp[(bh * SCH + c) * 64 + (e & 63)] = P;
    g_cq[(bh * SCH + c) * 64 + (e & 63)] = Q;
}

__global__ void __launch_bounds__(1024)
scanC_kernel()
{
    const int b = blockIdx.x >> 5;
    const int c = blockIdx.x & 31;
    const int e = threadIdx.x;
    const int bh = b * 16 + (e >> 6);
    const int d  = e & 63;
    // inline combine: h0 for this chunk from per-chunk (P,Q) of earlier chunks
    float hv = 0.f;
    for (int cc = 0; cc < c; cc++) {
        int i = (bh * SCH + cc) * 64 + d;
        hv = fmaf(g_cp[i], hv, g_cq[i]);
    }
    size_t base = ((size_t)b * LL + (size_t)c * SCL) * EB + e;
#pragma unroll 8
    for (int l = 0; l < SCL; l++) {
        size_t idx = base + (size_t)l * EB;
        float av = g_a[idx];
        float bv = g_b[idx];
        hv = fmaf(av, hv, bv);
        g_hs[idx] = hv;
    }
}

// ---------------- kernel 3: fused per-token epilogue ----------------
#define TOK 64
#define HS_STRIDE 68
#define POST_FLOATS 21248
#define POST_BYTES  (POST_FLOATS * 4)

__device__ __forceinline__ float grp8_sum(float v) {
    v += __shfl_xor_sync(0xffffffffu, v, 1);
    v += __shfl_xor_sync(0xffffffffu, v, 2);
    v += __shfl_xor_sync(0xffffffffu, v, 4);
    return v;
}

__device__ __forceinline__ void post_prefetch(uint32_t swc, uint32_t shs,
                                              const float* __restrict__ Wc,
                                              int h, long token0, int tid)
{
    const char* wsrc = (const char*)(Wc + (size_t)h * 4096);
#pragma unroll
    for (int i = 0; i < 4; i++) {
        int idx = tid + i * 256;
        cp_async16(swc + idx * 16, wsrc + idx * 16);
    }
#pragma unroll
    for (int i = 0; i < 4; i++) {
        int idx = tid + i * 256;
        int t = idx >> 4;
        int c = idx & 15;
        const char* hsrc = (const char*)(g_hs + (token0 + t) * (size_t)EB + h * 64);
        cp_async16(shs + (uint32_t)(t * HS_STRIDE * 4 + c * 16), hsrc + c * 16);
    }
}

__global__ void __launch_bounds__(256)
post_kernel(const float* __restrict__ Wc,  const float* __restrict__ bc,
            const float* __restrict__ head_w,
            const float* __restrict__ hn_g, const float* __restrict__ hn_b,
            const float* __restrict__ W1,  const float* __restrict__ b1,
            const float* __restrict__ W2,  const float* __restrict__ b2,
            const float* __restrict__ Wp,  const float* __restrict__ bp,
            const float* __restrict__ ng,  const float* __restrict__ nb,
            float* __restrict__ out)
{
    extern __shared__ float sm[];
    const int tid = threadIdx.x;
    const int tt  = tid >> 3;
    const int eg  = tid & 7;
    const int e0  = eg * 8;
    const long token0 = (long)blockIdx.x * TOK;
    const long tok0 = token0 + tt;
    const long tok1 = token0 + tt + 32;

    const uint32_t swc_u0 = smem_u32(sm);
    const uint32_t swc_u1 = smem_u32(sm + 4096);
    const uint32_t shs_u0 = smem_u32(sm + 8192);
    const uint32_t shs_u1 = smem_u32(sm + 8192 + TOK * HS_STRIDE);

    float dxv0[8], dxv1[8], acc0[8], acc1[8];
#pragma unroll
    for (int k = 0; k < 8; k++) {
        dxv0[k] = g_dx[tok0 * DH + e0 + k];
        dxv1[k] = g_dx[tok1 * DH + e0 + k];
        acc0[k] = dxv0[k];
        acc1[k] = dxv1[k];
    }

    post_prefetch(swc_u0, shs_u0, Wc, 0, token0, tid);
    cp_commit();

    for (int h = 0; h < NH; h++) {
        const int cur = h & 1;
        if (h + 1 < NH) {
            post_prefetch(cur ? swc_u0 : swc_u1, cur ? shs_u0 : shs_u1, Wc, h + 1, token0, tid);
            cp_commit();
            asm volatile("cp.async.wait_group 1;" ::: "memory");
        } else {
            asm volatile("cp.async.wait_group 0;" ::: "memory");
        }
        __syncthreads();

        const float* sWc = sm + (cur ? 4096 : 0);
        const float* sHs = sm + 8192 + (cur ? TOK * HS_STRIDE : 0);

        float o0[8], o1[8];
#pragma unroll
        for (int k = 0; k < 8; k++) {
            float bck = bc[h * DH + e0 + k];
            o0[k] = bck + dxv0[k];
            o1[k] = bck + dxv1[k];
        }
#pragma unroll 8
        for (int d = 0; d < 64; d++) {
            float hv0 = sHs[tt * HS_STRIDE + d];
            float hv1 = sHs[(tt + 32) * HS_STRIDE + d];
            float4 w0 = *(const float4*)&sWc[d * 64 + e0];
            float4 w1 = *(const float4*)&sWc[d * 64 + e0 + 4];
            o0[0] = fmaf(hv0, w0.x, o0[0]); o0[1] = fmaf(hv0, w0.y, o0[1]);
            o0[2] = fmaf(hv0, w0.z, o0[2]); o0[3] = fmaf(hv0, w0.w, o0[3]);
            o0[4] = fmaf(hv0, w1.x, o0[4]); o0[5] = fmaf(hv0, w1.y, o0[5]);
            o0[6] = fmaf(hv0, w1.z, o0[6]); o0[7] = fmaf(hv0, w1.w, o0[7]);
            o1[0] = fmaf(hv1, w0.x, o1[0]); o1[1] = fmaf(hv1, w0.y, o1[1]);
            o1[2] = fmaf(hv1, w0.z, o1[2]); o1[3] = fmaf(hv1, w0.w, o1[3]);
            o1[4] = fmaf(hv1, w1.x, o1[4]); o1[5] = fmaf(hv1, w1.y, o1[5]);
            o1[6] = fmaf(hv1, w1.z, o1[6]); o1[7] = fmaf(hv1, w1.w, o1[7]);
        }
        float s10 = 0.f, s20 = 0.f, s11 = 0.f, s21 = 0.f;
#pragma unroll
        for (int k = 0; k < 8; k++) {
            s10 += o0[k]; s20 += o0[k] * o0[k];
            s11 += o1[k]; s21 += o1[k] * o1[k];
        }
        s10 = grp8_sum(s10); s20 = grp8_sum(s20);
        s11 = grp8_sum(s11); s21 = grp8_sum(s21);
        float mean0 = s10 * (1.f / 64.f);
        float var0  = s20 * (1.f / 64.f) - mean0 * mean0;
        float rstd0 = rsqrtf(var0 + 1e-5f);
        float mean1 = s11 * (1.f / 64.f);
        float var1  = s21 * (1.f / 64.f) - mean1 * mean1;
        float rstd1 = rsqrtf(var1 + 1e-5f);
        float hw = head_w[h];
#pragma unroll
        for (int k = 0; k < 8; k++) {
            float gk = hn_g[h * DH + e0 + k];
            float bk = hn_b[h * DH + e0 + k];
            acc0[k] = fmaf(hw, (o0[k] - mean0) * rstd0 * gk + bk, acc0[k]);
            acc1[k] = fmaf(hw, (o1[k] - mean1) * rstd1 * gk + bk, acc1[k]);
        }
        __syncthreads();
    }

    float u0[8], u1[8];
    {
        float s10 = 0.f, s20 = 0.f, s11 = 0.f, s21 = 0.f;
#pragma unroll
        for (int k = 0; k < 8; k++) {
            acc0[k] *= (1.f / (float)NH);
            acc1[k] *= (1.f / (float)NH);
            s10 += acc0[k]; s20 += acc0[k] * acc0[k];
            s11 += acc1[k]; s21 += acc1[k] * acc1[k];
        }
        s10 = grp8_sum(s10); s20 = grp8_sum(s20);
        s11 = grp8_sum(s11); s21 = grp8_sum(s21);
        float mean0 = s10 * (1.f / 64.f);
        float var0  = s20 * (1.f / 64.f) - mean0 * mean0;
        float rstd0 = rsqrtf(var0 + 1e-5f);
        float mean1 = s11 * (1.f / 64.f);
        float var1  = s21 * (1.f / 64.f) - mean1 * mean1;
        float rstd1 = rsqrtf(var1 + 1e-5f);
#pragma unroll
        for (int k = 0; k < 8; k++) {
            float ngk = ng[e0 + k], nbk = nb[e0 + k];
            u0[k] = acc0[k] + (acc0[k] - mean0) * rstd0 * ngk + nbk;
            u1[k] = acc1[k] + (acc1[k] - mean1) * rstd1 * ngk + nbk;
        }
    }

    // ---- Phase B ----
    float* sW1c = sm;
    float* sW2c = sm + 4096;
    float* sU   = sm + 8192;
    float* sGc  = sm + 8192 + TOK * HS_STRIDE;
    float* sHo  = sm + 8192 + 2 * TOK * HS_STRIDE;

#pragma unroll
    for (int k = 0; k < 8; k++) {
        sU[tt * HS_STRIDE + e0 + k]        = u0[k];
        sU[(tt + 32) * HS_STRIDE + e0 + k] = u1[k];
    }

    float o20[8], o21[8];
#pragma unroll
    for (int k = 0; k < 8; k++) { o20[k] = b2[e0 + k]; o21[k] = o20[k]; }

    for (int jc = 0; jc < 4; jc++) {
        __syncthreads();
#pragma unroll
        for (int i = 0; i < 16; i++) {
            int idx = tid + i * 256;
            int d = idx >> 6, jj = idx & 63;
            sW1c[idx] = W1[d * 256 + jc * 64 + jj];
            sW2c[idx] = W2[(jc * 64 + (idx >> 6)) * 64 + (idx & 63)];
        }
        __syncthreads();
#pragma unroll
        for (int kk = 0; kk < 8; kk++) {
            int jl = eg + 8 * kk;
            float m0 = b1[jc * 64 + jl], m1 = m0;
#pragma unroll 8
            for (int d = 0; d < 64; d++) {
                float w = sW1c[d * 64 + jl];
                m0 = fmaf(sU[tt * HS_STRIDE + d], w, m0);
                m1 = fmaf(sU[(tt + 32) * HS_STRIDE + d], w, m1);
            }
            sGc[tt * HS_STRIDE + jl]        = 0.5f * m0 * (1.f + erff(m0 * 0.70710678118654752f));
            sGc[(tt + 32) * HS_STRIDE + jl] = 0.5f * m1 * (1.f + erff(m1 * 0.70710678118654752f));
        }
        __syncthreads();
#pragma unroll 8
        for (int jj = 0; jj < 64; jj++) {
            float gv0 = sGc[tt * HS_STRIDE + jj];
            float gv1 = sGc[(tt + 32) * HS_STRIDE + jj];
            float4 w0 = *(const float4*)&sW2c[jj * 64 + e0];
            float4 w1 = *(const float4*)&sW2c[jj * 64 + e0 + 4];
            o20[0] = fmaf(gv0, w0.x, o20[0]); o20[1] = fmaf(gv0, w0.y, o20[1]);
            o20[2] = fmaf(gv0, w0.z, o20[2]); o20[3] = fmaf(gv0, w0.w, o20[3]);
            o20[4] = fmaf(gv0, w1.x, o20[4]); o20[5] = fmaf(gv0, w1.y, o20[5]);
            o20[6] = fmaf(gv0, w1.z, o20[6]); o20[7] = fmaf(gv0, w1.w, o20[7]);
            o21[0] = fmaf(gv1, w0.x, o21[0]); o21[1] = fmaf(gv1, w0.y, o21[1]);
            o21[2] = fmaf(gv1, w0.z, o21[2]); o21[3] = fmaf(gv1, w0.w, o21[3]);
            o21[4] = fmaf(gv1, w1.x, o21[4]); o21[5] = fmaf(gv1, w1.y, o21[5]);
            o21[6] = fmaf(gv1, w1.z, o21[6]); o21[7] = fmaf(gv1, w1.w, o21[7]);
        }
    }

    __syncthreads();
#pragma unroll
    for (int k = 0; k < 8; k++) {
        sHo[tt * HS_STRIDE + e0 + k]        = u0[k] + o20[k];
        sHo[(tt + 32) * HS_STRIDE + e0 + k] = u1[k] + o21[k];
    }

    float fo0[8], fo1[8];
#pragma unroll
    for (int k = 0; k < 8; k++) { fo0[k] = bp[e0 + k]; fo1[k] = fo0[k]; }
    for (int dc = 0; dc < 2; dc++) {
        __syncthreads();
#pragma unroll
        for (int i = 0; i < 8; i++) {
            int idx = tid + i * 256;
            int d = idx >> 6, e = idx & 63;
            sW1c[idx] = Wp[(dc * 32 + d) * 64 + e];
        }
        __syncthreads();
#pragma unroll 8
        for (int d = 0; d < 32; d++) {
            float hv0 = sHo[tt * HS_STRIDE + dc * 32 + d];
            float hv1 = sHo[(tt + 32) * HS_STRIDE + dc * 32 + d];
            float4 w0 = *(const float4*)&sW1c[d * 64 + e0];
            float4 w1 = *(const float4*)&sW1c[d * 64 + e0 + 4];
            fo0[0] = fmaf(hv0, w0.x, fo0[0]); fo0[1] = fmaf(hv0, w0.y, fo0[1]);
            fo0[2] = fmaf(hv0, w0.z, fo0[2]); fo0[3] = fmaf(hv0, w0.w, fo0[3]);
            fo0[4] = fmaf(hv0, w1.x, fo0[4]); fo0[5] = fmaf(hv0, w1.y, fo0[5]);
            fo0[6] = fmaf(hv0, w1.z, fo0[6]); fo0[7] = fmaf(hv0, w1.w, fo0[7]);
            fo1[0] = fmaf(hv1, w0.x, fo1[0]); fo1[1] = fmaf(hv1, w0.y, fo1[1]);
            fo1[2] = fmaf(hv1, w0.z, fo1[2]); fo1[3] = fmaf(hv1, w0.w, fo1[3]);
            fo1[4] = fmaf(hv1, w1.x, fo1[4]); fo1[5] = fmaf(hv1, w1.y, fo1[5]);
            fo1[6] = fmaf(hv1, w1.z, fo1[6]); fo1[7] = fmaf(hv1, w1.w, fo1[7]);
        }
    }
#pragma unroll
    for (int k = 0; k < 8; k++) {
        out[tok0 * DH + e0 + k] = fo0[k];
        out[tok1 * DH + e0 + k] = fo1[k];
    }
}

// ---------------- launch ----------------
extern "C" void kernel_launch(void* const* d_in, const int* in_sizes, int n_in,
                              void* d_out, int out_size)
{
    const float* emb    = (const float*)d_in[0];
    const float* Wa     = (const float*)d_in[1];
    const float* ba     = (const float*)d_in[2];
    const float* Wb     = (const float*)d_in[3];
    const float* bb     = (const float*)d_in[4];
    const float* Wc     = (const float*)d_in[5];
    const float* bc     = (const float*)d_in[6];
    const float* head_w = (const float*)d_in[7];
    const float* hn_g   = (const float*)d_in[8];
    const float* hn_b   = (const float*)d_in[9];
    const float* Wd     = (const float*)d_in[10];
    const float* bd     = (const float*)d_in[11];
    const float* W1     = (const float*)d_in[12];
    const float* b1     = (const float*)d_in[13];
    const float* W2     = (const float*)d_in[14];
    const float* b2     = (const float*)d_in[15];
    const float* Wp     = (const float*)d_in[16];
    const float* bp     = (const float*)d_in[17];
    const float* ng     = (const float*)d_in[18];
    const float* nb     = (const float*)d_in[19];
    float* out = (float*)d_out;

    cudaFuncSetAttribute(gemm_tf32_kernel, cudaFuncAttributeMaxDynamicSharedMemorySize, GEMM_SMEM);
    cudaFuncSetAttribute(post_kernel, cudaFuncAttributeMaxDynamicSharedMemorySize, POST_BYTES);

    // launches 0,1,2: pack (steers ncu -s capture onto gemm at index 3)
    pack_ab_kernel<<<4096, 256>>>(Wa, 0);
    pack_ab_kernel<<<4096, 256>>>(Wb, 1024);
    pack_d_kernel<<<512, 256>>>(Wd);

    dim3 ggrid(GNP / 128, MT / 128);
    gemm_tf32_kernel<<<ggrid, 256, GEMM_SMEM>>>(emb, ba, bb, bd);

    scanA_kernel<<<BB * SCH, 1024>>>();
    scanC_kernel<<<BB * SCH, 1024>>>();

    post_kernel<<<MT / TOK, 256, POST_BYTES>>>(Wc, bc, head_w, hn_g, hn_b,
                                               W1, b1, W2, b2, Wp, bp, ng, nb, out);
}